// round 3
// baseline (speedup 1.0000x reference)
#include <cuda_runtime.h>
#include <cuda_bf16.h>
#include <cstdint>

#define NSAMP 4096

// ---------------- scratch (device globals, no allocations) ----------------
__device__ float g_h1[(size_t)NSAMP * 64 * 256];   // after conv1+relu+pool
__device__ float g_h2[(size_t)NSAMP * 128 * 128];  // after conv2+relu+pool
__device__ float g_feat[(size_t)NSAMP * 256];      // after conv3+relu+pool+mean
__device__ float g_z[(size_t)NSAMP * 128];         // after fc+relu+bn
__device__ float g_sq[NSAMP];                      // row norms of z
__device__ float g_fcwT[256 * 128];                // transposed fc weight

// ---------------- conv1: (N,1,512) -> (N,64,256) ----------------
// y[p] = sum_k w[oc][k] * x[p+k-49], relu, maxpool2
__global__ void k_conv1(const float* __restrict__ x,
                        const float* __restrict__ w,
                        const float* __restrict__ b) {
    __shared__ float xs[611];      // padded input: xs[i] = x[i-49]
    __shared__ float ws[64 * 100];
    const int n = blockIdx.x;
    const int tid = threadIdx.x;   // 256 threads
    const float* xn = x + (size_t)n * 512;

    for (int i = tid; i < 611; i += 256) {
        int j = i - 49;
        xs[i] = (j >= 0 && j < 512) ? xn[j] : 0.f;
    }
    for (int i = tid; i < 6400; i += 256) ws[i] = w[i];
    __syncthreads();

    const int pp = tid;  // pooled position 0..255 (conv positions 2pp, 2pp+1)
    float* out = g_h1 + (size_t)n * 64 * 256;

    for (int og = 0; og < 64; og += 8) {
        float a0[8], a1[8];
#pragma unroll
        for (int o = 0; o < 8; o++) { a0[o] = b[og + o]; a1[o] = a0[o]; }
        float xa = xs[2 * pp];
#pragma unroll 4
        for (int k = 0; k < 100; k++) {
            float xb = xs[2 * pp + k + 1];
#pragma unroll
            for (int o = 0; o < 8; o++) {
                float wv = ws[(og + o) * 100 + k];
                a0[o] = fmaf(wv, xa, a0[o]);
                a1[o] = fmaf(wv, xb, a1[o]);
            }
            xa = xb;
        }
#pragma unroll
        for (int o = 0; o < 8; o++) {
            float v = fmaxf(fmaxf(a0[o], a1[o]), 0.f);
            out[(og + o) * 256 + pp] = v;
        }
    }
}

// ---------------- conv2: (N,64,256) -> (N,128,128) ----------------
#define C2_SMEM ((64 * 260 + 64 * 320) * sizeof(float))
__global__ void k_conv2(const float* __restrict__ w, const float* __restrict__ b) {
    extern __shared__ float sm2[];
    float* ins = sm2;               // [64][260], ins[ic][j] = in[ic][j-2]
    float* ws  = sm2 + 64 * 260;    // [64 oc_local][64*5]
    const int n = blockIdx.x;
    const int ocBase = blockIdx.y * 64;
    const int tid = threadIdx.x;    // 512 threads
    const float* in = g_h1 + (size_t)n * 64 * 256;

    for (int i = tid; i < 64 * 260; i += 512) {
        int ic = i / 260, p = i % 260 - 2;
        ins[i] = (p >= 0 && p < 256) ? in[ic * 256 + p] : 0.f;
    }
    for (int i = tid; i < 64 * 320; i += 512) ws[i] = w[ocBase * 320 + i];
    __syncthreads();

    const int pp  = tid & 127;   // pooled pos (conv positions 2pp, 2pp+1)
    const int grp = tid >> 7;    // 0..3 -> this thread's 16 output channels
    float* out = g_h2 + (size_t)n * 128 * 128 + (size_t)ocBase * 128;

    for (int co = 0; co < 16; co += 8) {
        float a0[8], a1[8];
#pragma unroll
        for (int o = 0; o < 8; o++) {
            float bb = b[ocBase + grp * 16 + co + o];
            a0[o] = bb; a1[o] = bb;
        }
        for (int ic = 0; ic < 64; ic++) {
            const float* xr = ins + ic * 260 + 2 * pp;
            float x0 = xr[0], x1 = xr[1], x2 = xr[2], x3 = xr[3], x4 = xr[4], x5 = xr[5];
#pragma unroll
            for (int o = 0; o < 8; o++) {
                const float* wr = ws + (grp * 16 + co + o) * 320 + ic * 5;
                float w0 = wr[0], w1 = wr[1], w2 = wr[2], w3 = wr[3], w4 = wr[4];
                a0[o] = fmaf(w0, x0, fmaf(w1, x1, fmaf(w2, x2, fmaf(w3, x3, fmaf(w4, x4, a0[o])))));
                a1[o] = fmaf(w0, x1, fmaf(w1, x2, fmaf(w2, x3, fmaf(w3, x4, fmaf(w4, x5, a1[o])))));
            }
        }
#pragma unroll
        for (int o = 0; o < 8; o++) {
            float v = fmaxf(fmaxf(a0[o], a1[o]), 0.f);
            out[(grp * 16 + co + o) * 128 + pp] = v;
        }
    }
}

// ---------------- conv3 + pool + mean: (N,128,128) -> (N,256) ----------------
#define C3_SMEM ((128 * 130 + 64 * 384) * sizeof(float))
__global__ void k_conv3(const float* __restrict__ w, const float* __restrict__ b) {
    extern __shared__ float sm3[];
    float* ins = sm3;                // [128][130], ins[ic][j] = in[ic][j-1]
    float* ws  = sm3 + 128 * 130;    // [64 oc_local][128*3]
    __shared__ float part[16][8];    // per-warp partial sums
    const int n = blockIdx.x;
    const int ocBase = blockIdx.y * 64;
    const int tid = threadIdx.x;     // 512 threads
    const float* in = g_h2 + (size_t)n * 128 * 128;

    for (int i = tid; i < 128 * 130; i += 512) {
        int ic = i / 130, p = i % 130 - 1;
        ins[i] = (p >= 0 && p < 128) ? in[ic * 128 + p] : 0.f;
    }
    for (int i = tid; i < 64 * 384; i += 512) ws[i] = w[ocBase * 384 + i];
    __syncthreads();

    const int pp  = tid & 63;   // pooled pos 0..63
    const int grp = tid >> 6;   // 0..7 -> this thread's 8 output channels

    float a0[8], a1[8];
#pragma unroll
    for (int o = 0; o < 8; o++) {
        float bb = b[ocBase + grp * 8 + o];
        a0[o] = bb; a1[o] = bb;
    }
    for (int ic = 0; ic < 128; ic++) {
        const float* xr = ins + ic * 130 + 2 * pp;
        float x0 = xr[0], x1 = xr[1], x2 = xr[2], x3 = xr[3];
#pragma unroll
        for (int o = 0; o < 8; o++) {
            const float* wr = ws + (grp * 8 + o) * 384 + ic * 3;
            float w0 = wr[0], w1 = wr[1], w2 = wr[2];
            a0[o] = fmaf(w0, x0, fmaf(w1, x1, fmaf(w2, x2, a0[o])));
            a1[o] = fmaf(w0, x1, fmaf(w1, x2, fmaf(w2, x3, a1[o])));
        }
    }
    // pooled value at (oc, pp); sum over pp via warp reduce (2 warps per grp)
    float po[8];
#pragma unroll
    for (int o = 0; o < 8; o++) {
        po[o] = fmaxf(fmaxf(a0[o], a1[o]), 0.f);
#pragma unroll
        for (int off = 16; off; off >>= 1)
            po[o] += __shfl_xor_sync(0xFFFFFFFFu, po[o], off);
    }
    const int wi = tid >> 5;
    if ((tid & 31) == 0) {
#pragma unroll
        for (int o = 0; o < 8; o++) part[wi][o] = po[o];
    }
    __syncthreads();
    if (tid < 64) {
        int oc = tid, g = oc >> 3, o = oc & 7;
        float s = (part[2 * g][o] + part[2 * g + 1][o]) * (1.f / 64.f);
        g_feat[(size_t)n * 256 + ocBase + oc] = s;
    }
}

// ---------------- fc weight transpose ----------------
__global__ void k_fcT(const float* __restrict__ fcw) {
    int idx = blockIdx.x * blockDim.x + threadIdx.x;
    if (idx < 128 * 256) {
        int j = idx / 256, k = idx % 256;
        g_fcwT[k * 128 + j] = fcw[idx];
    }
}

// ---------------- fc + relu + bn -> z, sq ----------------
__global__ void k_fc(const float* __restrict__ fcb, const float* __restrict__ gamma,
                     const float* __restrict__ beta, const float* __restrict__ mean,
                     const float* __restrict__ var) {
    const int n = blockIdx.x;
    const int j = threadIdx.x;  // 128 threads
    __shared__ float fs[256];
    __shared__ float ps[4];
    fs[j]       = g_feat[(size_t)n * 256 + j];
    fs[j + 128] = g_feat[(size_t)n * 256 + 128 + j];
    __syncthreads();
    float acc = fcb[j];
#pragma unroll 8
    for (int k = 0; k < 256; k++) acc = fmaf(fs[k], g_fcwT[k * 128 + j], acc);
    acc = fmaxf(acc, 0.f);
    float z = gamma[j] * (acc - mean[j]) * rsqrtf(var[j] + 1e-5f) + beta[j];
    g_z[(size_t)n * 128 + j] = z;
    float s = z * z;
#pragma unroll
    for (int off = 16; off; off >>= 1) s += __shfl_xor_sync(0xFFFFFFFFu, s, off);
    if ((j & 31) == 0) ps[j >> 5] = s;
    __syncthreads();
    if (j == 0) g_sq[n] = ps[0] + ps[1] + ps[2] + ps[3];
}

// ---------------- pairwise distance + contrastive output ----------------
// samples_info is int32 on device (JAX default x64-disabled: astype(int64) is a no-op)
#define PAIR_SMEM (2 * 64 * 129 * sizeof(float))
__global__ void k_pair(const int* __restrict__ info, float* __restrict__ out) {
    extern __shared__ float pbuf[];
    float* As = pbuf;             // [64][129] rows ib..ib+63 of z
    float* Bs = pbuf + 64 * 129;  // [64][129] rows jb..jb+63 of z
    const int jb = blockIdx.x * 64;
    const int ib = blockIdx.y * 64;
    const int tid = threadIdx.x;  // 256 threads = 16x16

    for (int idx = tid; idx < 64 * 128; idx += 256) {
        int r = idx >> 7, k = idx & 127;
        As[r * 129 + k] = g_z[(size_t)(ib + r) * 128 + k];
        Bs[r * 129 + k] = g_z[(size_t)(jb + r) * 128 + k];
    }
    __syncthreads();

    const int tx = tid & 15, ty = tid >> 4;
    float c[4][4] = {};
    for (int k = 0; k < 128; k++) {
        float a[4], bb[4];
#pragma unroll
        for (int r = 0; r < 4; r++) a[r] = As[(ty * 4 + r) * 129 + k];
#pragma unroll
        for (int q = 0; q < 4; q++) bb[q] = Bs[(tx * 4 + q) * 129 + k];
#pragma unroll
        for (int r = 0; r < 4; r++)
#pragma unroll
            for (int q = 0; q < 4; q++) c[r][q] = fmaf(a[r], bb[q], c[r][q]);
    }

    float sqi[4], sqj[4];
    int wti[4], wtj[4];
    int gi[4], gj[4];
#pragma unroll
    for (int r = 0; r < 4; r++) {
        int i = ib + ty * 4 + r;
        sqi[r] = g_sq[i];
        wti[r] = info[2 * i];
        gi[r]  = info[2 * i + 1];
    }
#pragma unroll
    for (int q = 0; q < 4; q++) {
        int j = jb + tx * 4 + q;
        sqj[q] = g_sq[j];
        wtj[q] = info[2 * j];
        gj[q]  = info[2 * j + 1];
    }

#pragma unroll
    for (int r = 0; r < 4; r++) {
        int i = ib + ty * 4 + r;
        float4 v;
        float res[4];
#pragma unroll
        for (int q = 0; q < 4; q++) {
            int j = jb + tx * 4 + q;
            float d2 = sqi[r] + sqj[q] - 2.f * c[r][q];
            float d = sqrtf(fmaxf(d2, 0.f));
            bool y = (wti[r] == wtj[q]) && (gi[r] == 1) && (gj[q] == 1);
            float cl = y ? d : fmaxf(1.f - d, 0.f);
            res[q] = (i == j) ? 0.f : cl;
        }
        v.x = res[0]; v.y = res[1]; v.z = res[2]; v.w = res[3];
        *reinterpret_cast<float4*>(out + (size_t)i * 4096 + jb + tx * 4) = v;
    }
}

// ---------------- launch ----------------
extern "C" void kernel_launch(void* const* d_in, const int* in_sizes, int n_in,
                              void* d_out, int out_size) {
    const float* samples = (const float*)d_in[0];
    const int*   info    = (const int*)d_in[1];
    const float* w1   = (const float*)d_in[2];
    const float* b1   = (const float*)d_in[3];
    const float* w2   = (const float*)d_in[4];
    const float* b2   = (const float*)d_in[5];
    const float* w3   = (const float*)d_in[6];
    const float* b3   = (const float*)d_in[7];
    const float* fcw  = (const float*)d_in[8];
    const float* fcb  = (const float*)d_in[9];
    const float* gam  = (const float*)d_in[10];
    const float* bet  = (const float*)d_in[11];
    const float* bmu  = (const float*)d_in[12];
    const float* bva  = (const float*)d_in[13];
    float* out = (float*)d_out;

    cudaFuncSetAttribute(k_conv2, cudaFuncAttributeMaxDynamicSharedMemorySize, (int)C2_SMEM);
    cudaFuncSetAttribute(k_conv3, cudaFuncAttributeMaxDynamicSharedMemorySize, (int)C3_SMEM);
    cudaFuncSetAttribute(k_pair,  cudaFuncAttributeMaxDynamicSharedMemorySize, (int)PAIR_SMEM);

    k_conv1<<<NSAMP, 256>>>(samples, w1, b1);
    k_conv2<<<dim3(NSAMP, 2), 512, C2_SMEM>>>(w2, b2);
    k_conv3<<<dim3(NSAMP, 4), 512, C3_SMEM>>>(w3, b3);
    k_fcT<<<64, 512>>>(fcw);
    k_fc<<<NSAMP, 128>>>(fcb, gam, bet, bmu, bva);
    k_pair<<<dim3(64, 64), 256, PAIR_SMEM>>>(info, out);
}

// round 5
// speedup vs baseline: 1.3790x; 1.3790x over previous
#include <cuda_runtime.h>
#include <cuda_bf16.h>
#include <cstdint>

#define NSAMP 4096
typedef unsigned long long u64;

// ---------------- packed f32x2 helpers ----------------
__device__ __forceinline__ u64 pk2(float lo, float hi) {
    u64 r; asm("mov.b64 %0, {%1, %2};" : "=l"(r) : "f"(lo), "f"(hi)); return r;
}
__device__ __forceinline__ u64 bc2(float v) { return pk2(v, v); }
__device__ __forceinline__ void fma2(u64& d, u64 a, u64 b) {
    asm("fma.rn.f32x2 %0, %1, %2, %0;" : "+l"(d) : "l"(a), "l"(b));
}
__device__ __forceinline__ float2 up2(u64 v) {
    float2 f; asm("mov.b64 {%0, %1}, %2;" : "=f"(f.x), "=f"(f.y) : "l"(v)); return f;
}

// ---------------- scratch ----------------
__device__ float g_h1[(size_t)NSAMP * 64 * 256];   // after conv1+relu+pool
__device__ float g_h2[(size_t)NSAMP * 128 * 128];  // after conv2+relu+pool
__device__ float g_feat[(size_t)NSAMP * 256];      // after conv3+relu+pool+mean
__device__ float g_z[(size_t)NSAMP * 128];         // after fc+relu+bn
__device__ float g_sq[NSAMP];                      // row norms of z
__device__ float g_fcwT[256 * 128];                // transposed fc weight

// ---------------- conv1: (N,1,512) -> (N,64,256) ----------------
__global__ void k_conv1(const float* __restrict__ x,
                        const float* __restrict__ w,
                        const float* __restrict__ b) {
    __shared__ __align__(16) float wsT[100 * 66];  // wsT[k*66 + oc] (declared first, 16B aligned)
    __shared__ float xs[612];                      // xs[i] = x[i-49]
    const int n = blockIdx.x;
    const int tid = threadIdx.x;       // 256 threads
    const float* xn = x + (size_t)n * 512;

    for (int i = tid; i < 611; i += 256) {
        int j = i - 49;
        xs[i] = (j >= 0 && j < 512) ? xn[j] : 0.f;
    }
    for (int i = tid; i < 6400; i += 256) {
        int ol = i / 100, k = i % 100;
        wsT[k * 66 + ol] = w[i];
    }
    __syncthreads();

    const int pp = tid;  // pooled pos 0..255
    float* out = g_h1 + (size_t)n * 64 * 256;

    for (int og = 0; og < 64; og += 16) {   // 16 oc = 8 pairs per pass
        u64 acc0[8], acc1[8];
#pragma unroll
        for (int op = 0; op < 8; op++) {
            u64 bb = pk2(b[og + 2 * op], b[og + 2 * op + 1]);
            acc0[op] = bb; acc1[op] = bb;
        }
        float xa = xs[2 * pp];
#pragma unroll 4
        for (int k = 0; k < 100; k++) {
            float xb = xs[2 * pp + k + 1];
            u64 xap = bc2(xa), xbp = bc2(xb);
            const float* wrow = wsT + k * 66 + og;
#pragma unroll
            for (int op = 0; op < 8; op++) {
                u64 wp = *reinterpret_cast<const u64*>(wrow + 2 * op);
                fma2(acc0[op], wp, xap);
                fma2(acc1[op], wp, xbp);
            }
            xa = xb;
        }
#pragma unroll
        for (int op = 0; op < 8; op++) {
            float2 a0 = up2(acc0[op]), a1 = up2(acc1[op]);
            out[(og + 2 * op) * 256 + pp]     = fmaxf(fmaxf(a0.x, a1.x), 0.f);
            out[(og + 2 * op + 1) * 256 + pp] = fmaxf(fmaxf(a0.y, a1.y), 0.f);
        }
    }
}

// ---------------- conv2: (N,64,256) -> (N,128,128) ----------------
// 512 threads, 64-oc slice per block (grid.y = 2)
#define C2_SMEM ((64 * 260 + 320 * 66) * sizeof(float))
__global__ void k_conv2(const float* __restrict__ w, const float* __restrict__ b) {
    extern __shared__ float sm2[];
    float* ins = sm2;                // [64][260], ins[ic][j] = in[ic][j-2]
    float* wsT = sm2 + 64 * 260;     // wsT[(ic*5+k)*66 + ocLocal]  (byte off 66560, 8B-aligned)
    const int n = blockIdx.x;
    const int ocBase = blockIdx.y * 64;
    const int tid = threadIdx.x;     // 512 threads
    const float* in = g_h1 + (size_t)n * 64 * 256;

    for (int i = tid; i < 64 * 260; i += 512) {
        int ic = i / 260, p = i % 260 - 2;
        ins[i] = (p >= 0 && p < 256) ? in[ic * 256 + p] : 0.f;
    }
    for (int i = tid; i < 64 * 320; i += 512) {
        int ol = i / 320, m = i % 320;
        wsT[m * 66 + ol] = w[ocBase * 320 + i];
    }
    __syncthreads();

    const int pt  = tid & 63;    // pooled positions pt and pt+64
    const int ocl = (tid >> 6) * 8;  // 8 oc per thread (4 pairs)
    float* out = g_h2 + (size_t)n * 128 * 128 + (size_t)ocBase * 128;

    u64 aA0[4], aA1[4], aB0[4], aB1[4];
#pragma unroll
    for (int op = 0; op < 4; op++) {
        u64 bb = pk2(b[ocBase + ocl + 2 * op], b[ocBase + ocl + 2 * op + 1]);
        aA0[op] = bb; aA1[op] = bb; aB0[op] = bb; aB1[op] = bb;
    }

    for (int ic = 0; ic < 64; ic++) {
        const float* rowA = ins + ic * 260 + 2 * pt;
        const float* rowB = rowA + 128;
        float2 p01 = *reinterpret_cast<const float2*>(rowA);
        float2 p23 = *reinterpret_cast<const float2*>(rowA + 2);
        float2 p45 = *reinterpret_cast<const float2*>(rowA + 4);
        float2 q01 = *reinterpret_cast<const float2*>(rowB);
        float2 q23 = *reinterpret_cast<const float2*>(rowB + 2);
        float2 q45 = *reinterpret_cast<const float2*>(rowB + 4);
        u64 xA[6] = {bc2(p01.x), bc2(p01.y), bc2(p23.x), bc2(p23.y), bc2(p45.x), bc2(p45.y)};
        u64 xB[6] = {bc2(q01.x), bc2(q01.y), bc2(q23.x), bc2(q23.y), bc2(q45.x), bc2(q45.y)};
        const float* wbase = wsT + (ic * 5) * 66 + ocl;
#pragma unroll
        for (int k = 0; k < 5; k++) {
#pragma unroll
            for (int op = 0; op < 4; op++) {
                u64 wp = *reinterpret_cast<const u64*>(wbase + k * 66 + 2 * op);
                fma2(aA0[op], wp, xA[k]);
                fma2(aA1[op], wp, xA[k + 1]);
                fma2(aB0[op], wp, xB[k]);
                fma2(aB1[op], wp, xB[k + 1]);
            }
        }
    }
#pragma unroll
    for (int op = 0; op < 4; op++) {
        float2 vA0 = up2(aA0[op]), vA1 = up2(aA1[op]);
        float2 vB0 = up2(aB0[op]), vB1 = up2(aB1[op]);
        int r0 = (ocl + 2 * op) * 128, r1 = r0 + 128;
        out[r0 + pt]      = fmaxf(fmaxf(vA0.x, vA1.x), 0.f);
        out[r1 + pt]      = fmaxf(fmaxf(vA0.y, vA1.y), 0.f);
        out[r0 + pt + 64] = fmaxf(fmaxf(vB0.x, vB1.x), 0.f);
        out[r1 + pt + 64] = fmaxf(fmaxf(vB0.y, vB1.y), 0.f);
    }
}

// ---------------- conv3 + pool + mean: (N,128,128) -> (N,256) ----------------
// 256 threads, 64-oc slice per block (grid.y = 4)
#define C3_SMEM ((128 * 132 + 384 * 66) * sizeof(float))
__global__ void k_conv3(const float* __restrict__ w, const float* __restrict__ b) {
    extern __shared__ float sm3[];
    float* ins = sm3;                 // [128][132], ins[ic][j] = in[ic][j-1]
    float* wsT = sm3 + 128 * 132;     // wsT[(ic*3+k)*66 + ocLocal]  (byte off 67584, 8B-aligned)
    const int n = blockIdx.x;
    const int ocBase = blockIdx.y * 64;
    const int tid = threadIdx.x;      // 256 threads
    const float* in = g_h2 + (size_t)n * 128 * 128;

    for (int i = tid; i < 128 * 132; i += 256) {
        int ic = i / 132, p = i % 132 - 1;
        ins[i] = (p >= 0 && p < 128) ? in[ic * 128 + p] : 0.f;
    }
    for (int i = tid; i < 64 * 384; i += 256) {
        int ol = i / 384, m = i % 384;
        wsT[m * 66 + ol] = w[ocBase * 384 + i];
    }
    __syncthreads();

    const int pt  = tid & 31;        // pooled positions pt and pt+32
    const int ocl = (tid >> 5) * 8;  // warp id * 8 -> 8 oc per thread

    u64 aA0[4], aA1[4], aB0[4], aB1[4];
#pragma unroll
    for (int op = 0; op < 4; op++) {
        u64 bb = pk2(b[ocBase + ocl + 2 * op], b[ocBase + ocl + 2 * op + 1]);
        aA0[op] = bb; aA1[op] = bb; aB0[op] = bb; aB1[op] = bb;
    }

    for (int ic = 0; ic < 128; ic++) {
        const float* rowA = ins + ic * 132 + 2 * pt;
        const float* rowB = rowA + 64;
        float2 p01 = *reinterpret_cast<const float2*>(rowA);
        float2 p23 = *reinterpret_cast<const float2*>(rowA + 2);
        float2 q01 = *reinterpret_cast<const float2*>(rowB);
        float2 q23 = *reinterpret_cast<const float2*>(rowB + 2);
        u64 xA[4] = {bc2(p01.x), bc2(p01.y), bc2(p23.x), bc2(p23.y)};
        u64 xB[4] = {bc2(q01.x), bc2(q01.y), bc2(q23.x), bc2(q23.y)};
        const float* wbase = wsT + (ic * 3) * 66 + ocl;
#pragma unroll
        for (int k = 0; k < 3; k++) {
#pragma unroll
            for (int op = 0; op < 4; op++) {
                u64 wp = *reinterpret_cast<const u64*>(wbase + k * 66 + 2 * op);
                fma2(aA0[op], wp, xA[k]);
                fma2(aA1[op], wp, xA[k + 1]);
                fma2(aB0[op], wp, xB[k]);
                fma2(aB1[op], wp, xB[k + 1]);
            }
        }
    }
    // pooled+relu, then mean over 64 pooled positions (32 lanes x 2 sets)
#pragma unroll
    for (int op = 0; op < 4; op++) {
        float2 vA0 = up2(aA0[op]), vA1 = up2(aA1[op]);
        float2 vB0 = up2(aB0[op]), vB1 = up2(aB1[op]);
        float s0 = fmaxf(fmaxf(vA0.x, vA1.x), 0.f) + fmaxf(fmaxf(vB0.x, vB1.x), 0.f);
        float s1 = fmaxf(fmaxf(vA0.y, vA1.y), 0.f) + fmaxf(fmaxf(vB0.y, vB1.y), 0.f);
#pragma unroll
        for (int off = 16; off; off >>= 1) {
            s0 += __shfl_xor_sync(0xFFFFFFFFu, s0, off);
            s1 += __shfl_xor_sync(0xFFFFFFFFu, s1, off);
        }
        if (pt == 0) {
            g_feat[(size_t)n * 256 + ocBase + ocl + 2 * op]     = s0 * (1.f / 64.f);
            g_feat[(size_t)n * 256 + ocBase + ocl + 2 * op + 1] = s1 * (1.f / 64.f);
        }
    }
}

// ---------------- fc weight transpose ----------------
__global__ void k_fcT(const float* __restrict__ fcw) {
    int idx = blockIdx.x * blockDim.x + threadIdx.x;
    if (idx < 128 * 256) {
        int j = idx / 256, k = idx % 256;
        g_fcwT[k * 128 + j] = fcw[idx];
    }
}

// ---------------- fc + relu + bn -> z, sq ----------------
__global__ void k_fc(const float* __restrict__ fcb, const float* __restrict__ gamma,
                     const float* __restrict__ beta, const float* __restrict__ mean,
                     const float* __restrict__ var) {
    const int n = blockIdx.x;
    const int j = threadIdx.x;  // 128 threads
    __shared__ float fs[256];
    __shared__ float ps[4];
    fs[j]       = g_feat[(size_t)n * 256 + j];
    fs[j + 128] = g_feat[(size_t)n * 256 + 128 + j];
    __syncthreads();
    float acc = fcb[j];
#pragma unroll 8
    for (int k = 0; k < 256; k++) acc = fmaf(fs[k], g_fcwT[k * 128 + j], acc);
    acc = fmaxf(acc, 0.f);
    float z = gamma[j] * (acc - mean[j]) * rsqrtf(var[j] + 1e-5f) + beta[j];
    g_z[(size_t)n * 128 + j] = z;
    float s = z * z;
#pragma unroll
    for (int off = 16; off; off >>= 1) s += __shfl_xor_sync(0xFFFFFFFFu, s, off);
    if ((j & 31) == 0) ps[j >> 5] = s;
    __syncthreads();
    if (j == 0) g_sq[n] = ps[0] + ps[1] + ps[2] + ps[3];
}

// ---------------- pairwise distance + contrastive output ----------------
#define PAIR_SMEM ((64 * 130 + 128 * 66) * sizeof(float))
__global__ void k_pair(const int* __restrict__ info, float* __restrict__ out) {
    extern __shared__ float pbuf[];
    float* As = pbuf;             // [64][130] rows ib..ib+63 of z (stride keeps Bs 8B-aligned)
    float* Bs = pbuf + 64 * 130;  // transposed [k][66] of rows jb..jb+63
    const int jb = blockIdx.x * 64;
    const int ib = blockIdx.y * 64;
    const int tid = threadIdx.x;  // 256 threads = 16x16

    for (int idx = tid; idx < 64 * 128; idx += 256) {
        int r = idx >> 7, k = idx & 127;
        As[r * 130 + k] = g_z[(size_t)(ib + r) * 128 + k];
        Bs[k * 66 + r]  = g_z[(size_t)(jb + r) * 128 + k];
    }
    __syncthreads();

    const int tx = tid & 15, ty = tid >> 4;
    u64 c[4][2];
#pragma unroll
    for (int r = 0; r < 4; r++) { c[r][0] = 0ull; c[r][1] = 0ull; }
    for (int k = 0; k < 128; k++) {
        u64 bp0 = *reinterpret_cast<const u64*>(Bs + k * 66 + 4 * tx);
        u64 bp1 = *reinterpret_cast<const u64*>(Bs + k * 66 + 4 * tx + 2);
#pragma unroll
        for (int r = 0; r < 4; r++) {
            u64 ap = bc2(As[(ty * 4 + r) * 130 + k]);
            fma2(c[r][0], ap, bp0);
            fma2(c[r][1], ap, bp1);
        }
    }

    float sqi[4], sqj[4];
    int wti[4], wtj[4], gi[4], gj[4];
#pragma unroll
    for (int r = 0; r < 4; r++) {
        int i = ib + ty * 4 + r;
        sqi[r] = g_sq[i]; wti[r] = info[2 * i]; gi[r] = info[2 * i + 1];
    }
#pragma unroll
    for (int q = 0; q < 4; q++) {
        int j = jb + tx * 4 + q;
        sqj[q] = g_sq[j]; wtj[q] = info[2 * j]; gj[q] = info[2 * j + 1];
    }

#pragma unroll
    for (int r = 0; r < 4; r++) {
        int i = ib + ty * 4 + r;
        float cc[4];
        float2 c0 = up2(c[r][0]), c1 = up2(c[r][1]);
        cc[0] = c0.x; cc[1] = c0.y; cc[2] = c1.x; cc[3] = c1.y;
        float4 v; float res[4];
#pragma unroll
        for (int q = 0; q < 4; q++) {
            int j = jb + tx * 4 + q;
            float d2 = sqi[r] + sqj[q] - 2.f * cc[q];
            float d = sqrtf(fmaxf(d2, 0.f));
            bool y = (wti[r] == wtj[q]) && (gi[r] == 1) && (gj[q] == 1);
            float cl = y ? d : fmaxf(1.f - d, 0.f);
            res[q] = (i == j) ? 0.f : cl;
        }
        v.x = res[0]; v.y = res[1]; v.z = res[2]; v.w = res[3];
        *reinterpret_cast<float4*>(out + (size_t)i * 4096 + jb + tx * 4) = v;
    }
}

// ---------------- launch ----------------
extern "C" void kernel_launch(void* const* d_in, const int* in_sizes, int n_in,
                              void* d_out, int out_size) {
    const float* samples = (const float*)d_in[0];
    const int*   info    = (const int*)d_in[1];
    const float* w1  = (const float*)d_in[2];
    const float* b1  = (const float*)d_in[3];
    const float* w2  = (const float*)d_in[4];
    const float* b2  = (const float*)d_in[5];
    const float* w3  = (const float*)d_in[6];
    const float* b3  = (const float*)d_in[7];
    const float* fcw = (const float*)d_in[8];
    const float* fcb = (const float*)d_in[9];
    const float* gam = (const float*)d_in[10];
    const float* bet = (const float*)d_in[11];
    const float* bmu = (const float*)d_in[12];
    const float* bva = (const float*)d_in[13];
    float* out = (float*)d_out;

    cudaFuncSetAttribute(k_conv2, cudaFuncAttributeMaxDynamicSharedMemorySize, (int)C2_SMEM);
    cudaFuncSetAttribute(k_conv3, cudaFuncAttributeMaxDynamicSharedMemorySize, (int)C3_SMEM);
    cudaFuncSetAttribute(k_pair,  cudaFuncAttributeMaxDynamicSharedMemorySize, (int)PAIR_SMEM);

    k_conv1<<<NSAMP, 256>>>(samples, w1, b1);
    k_conv2<<<dim3(NSAMP, 2), 512, C2_SMEM>>>(w2, b2);
    k_conv3<<<dim3(NSAMP, 4), 256, C3_SMEM>>>(w3, b3);
    k_fcT<<<64, 512>>>(fcw);
    k_fc<<<NSAMP, 128>>>(fcb, gam, bet, bmu, bva);
    k_pair<<<dim3(64, 64), 256, PAIR_SMEM>>>(info, out);
}

// round 6
// speedup vs baseline: 2.2221x; 1.6114x over previous
#include <cuda_runtime.h>
#include <cuda_bf16.h>
#include <cstdint>

#define NSAMP 4096
typedef unsigned long long u64;
typedef unsigned int u32;

// ---------------- packed f32x2 helpers (conv1) ----------------
__device__ __forceinline__ u64 pk2(float lo, float hi) {
    u64 r; asm("mov.b64 %0, {%1, %2};" : "=l"(r) : "f"(lo), "f"(hi)); return r;
}
__device__ __forceinline__ u64 bc2(float v) { return pk2(v, v); }
__device__ __forceinline__ void fma2(u64& d, u64 a, u64 b) {
    asm("fma.rn.f32x2 %0, %1, %2, %0;" : "+l"(d) : "l"(a), "l"(b));
}
__device__ __forceinline__ float2 up2(u64 v) {
    float2 f; asm("mov.b64 {%0, %1}, %2;" : "=f"(f.x), "=f"(f.y) : "l"(v)); return f;
}

// ---------------- bf16 split + mma helpers ----------------
__device__ __forceinline__ void bsplit(float x, __nv_bfloat16* h, __nv_bfloat16* l) {
    __nv_bfloat16 hh = __float2bfloat16_rn(x);
    *h = hh;
    *l = __float2bfloat16_rn(x - __bfloat162float(hh));
}
__device__ __forceinline__ void mma_bf16(float* d, const u32* a, u32 b0, u32 b1) {
    asm("mma.sync.aligned.m16n8k16.row.col.f32.bf16.bf16.f32 "
        "{%0,%1,%2,%3},{%4,%5,%6,%7},{%8,%9},{%0,%1,%2,%3};"
        : "+f"(d[0]), "+f"(d[1]), "+f"(d[2]), "+f"(d[3])
        : "r"(a[0]), "r"(a[1]), "r"(a[2]), "r"(a[3]), "r"(b0), "r"(b1));
}

// ---------------- scratch ----------------
__device__ __nv_bfloat16 g_h1h[(size_t)NSAMP * 256 * 64];   // conv1 out [n][pos][oc] split-hi
__device__ __nv_bfloat16 g_h1l[(size_t)NSAMP * 256 * 64];
__device__ __nv_bfloat16 g_h2h[(size_t)NSAMP * 128 * 128];  // conv2 out [n][pp][oc]
__device__ __nv_bfloat16 g_h2l[(size_t)NSAMP * 128 * 128];
__device__ __nv_bfloat16 g_w2h[5 * 128 * 64];               // [k][oc][ic]
__device__ __nv_bfloat16 g_w2l[5 * 128 * 64];
__device__ __nv_bfloat16 g_w3h[3 * 256 * 128];              // [k][oc][ic]
__device__ __nv_bfloat16 g_w3l[3 * 256 * 128];
__device__ float g_feat[(size_t)NSAMP * 256];
__device__ float g_z[(size_t)NSAMP * 128];
__device__ float g_sq[NSAMP];
__device__ float g_fcwT[256 * 128];

// ---------------- weight split prep ----------------
__global__ void k_split_w2(const float* __restrict__ w2) {
    int idx = blockIdx.x * blockDim.x + threadIdx.x;  // oc*64*5 layout in src
    if (idx < 128 * 64 * 5) {
        int oc = idx / 320, rem = idx % 320, ic = rem / 5, k = rem % 5;
        int dst = (k * 128 + oc) * 64 + ic;
        bsplit(w2[idx], &g_w2h[dst], &g_w2l[dst]);
    }
}
__global__ void k_split_w3(const float* __restrict__ w3) {
    int idx = blockIdx.x * blockDim.x + threadIdx.x;
    if (idx < 256 * 128 * 3) {
        int oc = idx / 384, rem = idx % 384, ic = rem / 3, k = rem % 3;
        int dst = (k * 256 + oc) * 128 + ic;
        bsplit(w3[idx], &g_w3h[dst], &g_w3l[dst]);
    }
}

// ---------------- conv1: (N,1,512) -> (N,256 pos,64 oc) split-bf16, FFMA2 ----------------
__global__ void k_conv1(const float* __restrict__ x,
                        const float* __restrict__ w,
                        const float* __restrict__ b) {
    __shared__ __align__(16) float wsT[100 * 66];  // wsT[k*66 + oc]
    __shared__ float xs[612];                      // xs[i] = x[i-49]
    const int n = blockIdx.x;
    const int tid = threadIdx.x;       // 256 threads
    const float* xn = x + (size_t)n * 512;

    for (int i = tid; i < 611; i += 256) {
        int j = i - 49;
        xs[i] = (j >= 0 && j < 512) ? xn[j] : 0.f;
    }
    for (int i = tid; i < 6400; i += 256) {
        int ol = i / 100, k = i % 100;
        wsT[k * 66 + ol] = w[i];
    }
    __syncthreads();

    const int pp = tid;  // pooled pos 0..255
    const size_t obase = ((size_t)n * 256 + pp) * 64;

    for (int og = 0; og < 64; og += 16) {
        u64 acc0[8], acc1[8];
#pragma unroll
        for (int op = 0; op < 8; op++) {
            u64 bb = pk2(b[og + 2 * op], b[og + 2 * op + 1]);
            acc0[op] = bb; acc1[op] = bb;
        }
        float xa = xs[2 * pp];
#pragma unroll 4
        for (int k = 0; k < 100; k++) {
            float xb = xs[2 * pp + k + 1];
            u64 xap = bc2(xa), xbp = bc2(xb);
            const float* wrow = wsT + k * 66 + og;
#pragma unroll
            for (int op = 0; op < 8; op++) {
                u64 wp = *reinterpret_cast<const u64*>(wrow + 2 * op);
                fma2(acc0[op], wp, xap);
                fma2(acc1[op], wp, xbp);
            }
            xa = xb;
        }
#pragma unroll
        for (int op = 0; op < 8; op++) {
            float2 a0 = up2(acc0[op]), a1 = up2(acc1[op]);
            float v0 = fmaxf(fmaxf(a0.x, a1.x), 0.f);
            float v1 = fmaxf(fmaxf(a0.y, a1.y), 0.f);
            bsplit(v0, &g_h1h[obase + og + 2 * op],     &g_h1l[obase + og + 2 * op]);
            bsplit(v1, &g_h1h[obase + og + 2 * op + 1], &g_h1l[obase + og + 2 * op + 1]);
        }
    }
}

// ---------------- conv2 (tensor): per-sample GEMM, 5 row-shifts ----------------
// X smem [260 rows][72 elems] (row r = input pos r-2), bf16 hi/lo
#define C2_XS 72
#define C2_SMEM (2 * 260 * C2_XS * 2)
__global__ void __launch_bounds__(512, 1) k_conv2(const float* __restrict__ b2) {
    extern __shared__ __nv_bfloat16 sm[];
    __nv_bfloat16* Xh = sm;                 // 260*72 = 18720 elems
    __nv_bfloat16* Xl = sm + 260 * C2_XS;
    const int n = blockIdx.x;
    const int tid = threadIdx.x;  // 512
    const int lane = tid & 31, w = tid >> 5;

    // zero pad rows 0,1,258,259 (36 words each)
    for (int i = tid; i < 144; i += 512) {
        int rr = i / 36, cw = i % 36;
        int r = (rr < 2) ? rr : 256 + rr;   // 0,1,258,259
        *(u32*)(Xh + r * C2_XS + 2 * cw) = 0u;
        *(u32*)(Xl + r * C2_XS + 2 * cw) = 0u;
    }
    // load rows 2..257 from g_h1 (u32 = 2 bf16)
    for (int i = tid; i < 8192; i += 512) {
        int r = i >> 5, cw = i & 31;
        u32 vh = ((const u32*)g_h1h)[((size_t)n * 256 + r) * 32 + cw];
        u32 vl = ((const u32*)g_h1l)[((size_t)n * 256 + r) * 32 + cw];
        *(u32*)(Xh + (r + 2) * C2_XS + 2 * cw) = vh;
        *(u32*)(Xl + (r + 2) * C2_XS + 2 * cw) = vl;
    }
    __syncthreads();

    const int g = lane >> 2, tc = lane & 3;
    const int m0 = (w & 7) * 16;        // oc tile
    const int n0 = (w >> 3) * 128;      // position half

    float acc[16][4];
#pragma unroll
    for (int j = 0; j < 16; j++) { acc[j][0] = acc[j][1] = acc[j][2] = acc[j][3] = 0.f; }

    for (int s = 0; s < 5; s++) {
#pragma unroll
        for (int kt = 0; kt < 4; kt++) {
            const int k0 = kt * 16;
            const __nv_bfloat16* wh = g_w2h + ((size_t)(s * 128 + m0 + g)) * 64 + k0 + 2 * tc;
            const __nv_bfloat16* wl = g_w2l + ((size_t)(s * 128 + m0 + g)) * 64 + k0 + 2 * tc;
            u32 ah[4], al[4];
            ah[0] = *(const u32*)(wh);
            ah[1] = *(const u32*)(wh + 8 * 64);
            ah[2] = *(const u32*)(wh + 8);
            ah[3] = *(const u32*)(wh + 8 * 64 + 8);
            al[0] = *(const u32*)(wl);
            al[1] = *(const u32*)(wl + 8 * 64);
            al[2] = *(const u32*)(wl + 8);
            al[3] = *(const u32*)(wl + 8 * 64 + 8);
            const int rbase = n0 + g + s;
#pragma unroll
            for (int j = 0; j < 16; j++) {
                const __nv_bfloat16* xr = Xh + (rbase + 8 * j) * C2_XS + k0 + 2 * tc;
                const __nv_bfloat16* yr = Xl + (rbase + 8 * j) * C2_XS + k0 + 2 * tc;
                u32 bh0 = *(const u32*)xr, bh1 = *(const u32*)(xr + 8);
                u32 bl0 = *(const u32*)yr, bl1 = *(const u32*)(yr + 8);
                mma_bf16(acc[j], ah, bh0, bh1);
                mma_bf16(acc[j], ah, bl0, bl1);
                mma_bf16(acc[j], al, bh0, bh1);
            }
        }
    }

    const float bi0 = b2[m0 + g], bi1 = b2[m0 + g + 8];
    __syncthreads();  // done reading X; reuse smem for output staging

    __nv_bfloat16* Sh = sm;                 // [128 pp][132]
    __nv_bfloat16* Sl = sm + 260 * C2_XS;
#pragma unroll
    for (int j = 0; j < 16; j++) {
        int pp = n0 / 2 + 4 * j + tc;
        float v0 = fmaxf(fmaxf(acc[j][0] + bi0, acc[j][1] + bi0), 0.f);
        float v1 = fmaxf(fmaxf(acc[j][2] + bi1, acc[j][3] + bi1), 0.f);
        bsplit(v0, &Sh[pp * 132 + m0 + g],     &Sl[pp * 132 + m0 + g]);
        bsplit(v1, &Sh[pp * 132 + m0 + g + 8], &Sl[pp * 132 + m0 + g + 8]);
    }
    __syncthreads();
    for (int i = tid; i < 8192; i += 512) {   // 128*128/2 u32
        int pp = i >> 6, cw = i & 63;
        ((u32*)g_h2h)[((size_t)n * 128 + pp) * 64 + cw] = *(const u32*)(Sh + pp * 132 + 2 * cw);
        ((u32*)g_h2l)[((size_t)n * 128 + pp) * 64 + cw] = *(const u32*)(Sl + pp * 132 + 2 * cw);
    }
}

// ---------------- conv3 (tensor) + pool + mean ----------------
// X smem [130 rows][136 elems] (row r = input pos r-1)
#define C3_XS 136
#define C3_SMEM (2 * 130 * C3_XS * 2)
__global__ void __launch_bounds__(512, 1) k_conv3(const float* __restrict__ b3) {
    extern __shared__ __nv_bfloat16 sm3[];
    __nv_bfloat16* Xh = sm3;                 // 130*136 = 17680 elems
    __nv_bfloat16* Xl = sm3 + 130 * C3_XS;
    const int n = blockIdx.x;
    const int tid = threadIdx.x;  // 512
    const int lane = tid & 31, w = tid >> 5;

    // zero rows 0 and 129 (68 words each)
    for (int i = tid; i < 136; i += 512) {
        int rr = i / 68, cw = i % 68;
        int r = rr ? 129 : 0;
        *(u32*)(Xh + r * C3_XS + 2 * cw) = 0u;
        *(u32*)(Xl + r * C3_XS + 2 * cw) = 0u;
    }
    // rows 1..128 <- g_h2[n][pp=r-1][*]
    for (int i = tid; i < 8192; i += 512) {
        int r = i >> 6, cw = i & 63;
        u32 vh = ((const u32*)g_h2h)[((size_t)n * 128 + r) * 64 + cw];
        u32 vl = ((const u32*)g_h2l)[((size_t)n * 128 + r) * 64 + cw];
        *(u32*)(Xh + (r + 1) * C3_XS + 2 * cw) = vh;
        *(u32*)(Xl + (r + 1) * C3_XS + 2 * cw) = vl;
    }
    __syncthreads();

    const int g = lane >> 2, tc = lane & 3;
    const int m0 = w * 16;   // 16 warps cover 256 oc

    float acc[16][4];
#pragma unroll
    for (int j = 0; j < 16; j++) { acc[j][0] = acc[j][1] = acc[j][2] = acc[j][3] = 0.f; }

    for (int s = 0; s < 3; s++) {
#pragma unroll
        for (int kt = 0; kt < 8; kt++) {
            const int k0 = kt * 16;
            const __nv_bfloat16* wh = g_w3h + ((size_t)(s * 256 + m0 + g)) * 128 + k0 + 2 * tc;
            const __nv_bfloat16* wl = g_w3l + ((size_t)(s * 256 + m0 + g)) * 128 + k0 + 2 * tc;
            u32 ah[4], al[4];
            ah[0] = *(const u32*)(wh);
            ah[1] = *(const u32*)(wh + 8 * 128);
            ah[2] = *(const u32*)(wh + 8);
            ah[3] = *(const u32*)(wh + 8 * 128 + 8);
            al[0] = *(const u32*)(wl);
            al[1] = *(const u32*)(wl + 8 * 128);
            al[2] = *(const u32*)(wl + 8);
            al[3] = *(const u32*)(wl + 8 * 128 + 8);
            const int rbase = g + s;
#pragma unroll
            for (int j = 0; j < 16; j++) {
                const __nv_bfloat16* xr = Xh + (rbase + 8 * j) * C3_XS + k0 + 2 * tc;
                const __nv_bfloat16* yr = Xl + (rbase + 8 * j) * C3_XS + k0 + 2 * tc;
                u32 bh0 = *(const u32*)xr, bh1 = *(const u32*)(xr + 8);
                u32 bl0 = *(const u32*)yr, bl1 = *(const u32*)(yr + 8);
                mma_bf16(acc[j], ah, bh0, bh1);
                mma_bf16(acc[j], ah, bl0, bl1);
                mma_bf16(acc[j], al, bh0, bh1);
            }
        }
    }

    const float bi0 = b3[m0 + g], bi1 = b3[m0 + g + 8];
    float s0 = 0.f, s1 = 0.f;
#pragma unroll
    for (int j = 0; j < 16; j++) {
        s0 += fmaxf(fmaxf(acc[j][0] + bi0, acc[j][1] + bi0), 0.f);
        s1 += fmaxf(fmaxf(acc[j][2] + bi1, acc[j][3] + bi1), 0.f);
    }
    // sum over tc quad (each thread covered pp = 4j+tc)
    s0 += __shfl_xor_sync(0xFFFFFFFFu, s0, 1);
    s0 += __shfl_xor_sync(0xFFFFFFFFu, s0, 2);
    s1 += __shfl_xor_sync(0xFFFFFFFFu, s1, 1);
    s1 += __shfl_xor_sync(0xFFFFFFFFu, s1, 2);
    if (tc == 0) {
        g_feat[(size_t)n * 256 + m0 + g]     = s0 * (1.f / 64.f);
        g_feat[(size_t)n * 256 + m0 + g + 8] = s1 * (1.f / 64.f);
    }
}

// ---------------- fc weight transpose ----------------
__global__ void k_fcT(const float* __restrict__ fcw) {
    int idx = blockIdx.x * blockDim.x + threadIdx.x;
    if (idx < 128 * 256) {
        int j = idx / 256, k = idx % 256;
        g_fcwT[k * 128 + j] = fcw[idx];
    }
}

// ---------------- fc + relu + bn -> z, sq ----------------
__global__ void k_fc(const float* __restrict__ fcb, const float* __restrict__ gamma,
                     const float* __restrict__ beta, const float* __restrict__ mean,
                     const float* __restrict__ var) {
    const int n = blockIdx.x;
    const int j = threadIdx.x;  // 128 threads
    __shared__ float fs[256];
    __shared__ float ps[4];
    fs[j]       = g_feat[(size_t)n * 256 + j];
    fs[j + 128] = g_feat[(size_t)n * 256 + 128 + j];
    __syncthreads();
    float acc = fcb[j];
#pragma unroll 8
    for (int k = 0; k < 256; k++) acc = fmaf(fs[k], g_fcwT[k * 128 + j], acc);
    acc = fmaxf(acc, 0.f);
    float z = gamma[j] * (acc - mean[j]) * rsqrtf(var[j] + 1e-5f) + beta[j];
    g_z[(size_t)n * 128 + j] = z;
    float s = z * z;
#pragma unroll
    for (int off = 16; off; off >>= 1) s += __shfl_xor_sync(0xFFFFFFFFu, s, off);
    if ((j & 31) == 0) ps[j >> 5] = s;
    __syncthreads();
    if (j == 0) g_sq[n] = ps[0] + ps[1] + ps[2] + ps[3];
}

// ---------------- pairwise distance + contrastive output (FFMA2) ----------------
#define PAIR_SMEM ((64 * 130 + 128 * 66) * sizeof(float))
__global__ void k_pair(const int* __restrict__ info, float* __restrict__ out) {
    extern __shared__ float pbuf[];
    float* As = pbuf;             // [64][130]
    float* Bs = pbuf + 64 * 130;  // [k][66]
    const int jb = blockIdx.x * 64;
    const int ib = blockIdx.y * 64;
    const int tid = threadIdx.x;  // 256

    for (int idx = tid; idx < 64 * 128; idx += 256) {
        int r = idx >> 7, k = idx & 127;
        As[r * 130 + k] = g_z[(size_t)(ib + r) * 128 + k];
        Bs[k * 66 + r]  = g_z[(size_t)(jb + r) * 128 + k];
    }
    __syncthreads();

    const int tx = tid & 15, ty = tid >> 4;
    u64 c[4][2];
#pragma unroll
    for (int r = 0; r < 4; r++) { c[r][0] = 0ull; c[r][1] = 0ull; }
    for (int k = 0; k < 128; k++) {
        u64 bp0 = *reinterpret_cast<const u64*>(Bs + k * 66 + 4 * tx);
        u64 bp1 = *reinterpret_cast<const u64*>(Bs + k * 66 + 4 * tx + 2);
#pragma unroll
        for (int r = 0; r < 4; r++) {
            u64 ap = bc2(As[(ty * 4 + r) * 130 + k]);
            fma2(c[r][0], ap, bp0);
            fma2(c[r][1], ap, bp1);
        }
    }

    float sqi[4], sqj[4];
    int wti[4], wtj[4], gi[4], gj[4];
#pragma unroll
    for (int r = 0; r < 4; r++) {
        int i = ib + ty * 4 + r;
        sqi[r] = g_sq[i]; wti[r] = info[2 * i]; gi[r] = info[2 * i + 1];
    }
#pragma unroll
    for (int q = 0; q < 4; q++) {
        int j = jb + tx * 4 + q;
        sqj[q] = g_sq[j]; wtj[q] = info[2 * j]; gj[q] = info[2 * j + 1];
    }

#pragma unroll
    for (int r = 0; r < 4; r++) {
        int i = ib + ty * 4 + r;
        float cc[4];
        float2 c0 = up2(c[r][0]), c1 = up2(c[r][1]);
        cc[0] = c0.x; cc[1] = c0.y; cc[2] = c1.x; cc[3] = c1.y;
        float4 v; float res[4];
#pragma unroll
        for (int q = 0; q < 4; q++) {
            int j = jb + tx * 4 + q;
            float d2 = sqi[r] + sqj[q] - 2.f * cc[q];
            float d = sqrtf(fmaxf(d2, 0.f));
            bool y = (wti[r] == wtj[q]) && (gi[r] == 1) && (gj[q] == 1);
            float cl = y ? d : fmaxf(1.f - d, 0.f);
            res[q] = (i == j) ? 0.f : cl;
        }
        v.x = res[0]; v.y = res[1]; v.z = res[2]; v.w = res[3];
        *reinterpret_cast<float4*>(out + (size_t)i * 4096 + jb + tx * 4) = v;
    }
}

// ---------------- launch ----------------
extern "C" void kernel_launch(void* const* d_in, const int* in_sizes, int n_in,
                              void* d_out, int out_size) {
    const float* samples = (const float*)d_in[0];
    const int*   info    = (const int*)d_in[1];
    const float* w1  = (const float*)d_in[2];
    const float* b1  = (const float*)d_in[3];
    const float* w2  = (const float*)d_in[4];
    const float* b2  = (const float*)d_in[5];
    const float* w3  = (const float*)d_in[6];
    const float* b3  = (const float*)d_in[7];
    const float* fcw = (const float*)d_in[8];
    const float* fcb = (const float*)d_in[9];
    const float* gam = (const float*)d_in[10];
    const float* bet = (const float*)d_in[11];
    const float* bmu = (const float*)d_in[12];
    const float* bva = (const float*)d_in[13];
    float* out = (float*)d_out;

    cudaFuncSetAttribute(k_conv2, cudaFuncAttributeMaxDynamicSharedMemorySize, (int)C2_SMEM);
    cudaFuncSetAttribute(k_conv3, cudaFuncAttributeMaxDynamicSharedMemorySize, (int)C3_SMEM);
    cudaFuncSetAttribute(k_pair,  cudaFuncAttributeMaxDynamicSharedMemorySize, (int)PAIR_SMEM);

    k_split_w2<<<160, 256>>>(w2);
    k_split_w3<<<384, 256>>>(w3);
    k_conv1<<<NSAMP, 256>>>(samples, w1, b1);
    k_conv2<<<NSAMP, 512, C2_SMEM>>>(b2);
    k_conv3<<<NSAMP, 512, C3_SMEM>>>(b3);
    k_fcT<<<64, 512>>>(fcw);
    k_fc<<<NSAMP, 128>>>(fcb, gam, bet, bmu, bva);
    k_pair<<<dim3(64, 64), 256, PAIR_SMEM>>>(info, out);
}

// round 8
// speedup vs baseline: 4.0674x; 1.8304x over previous
#include <cuda_runtime.h>
#include <cuda_bf16.h>
#include <cstdint>

#define NSAMP 4096
typedef unsigned long long u64;
typedef unsigned int u32;

// ---------------- packed f32x2 helpers ----------------
__device__ __forceinline__ u64 pk2(float lo, float hi) {
    u64 r; asm("mov.b64 %0, {%1, %2};" : "=l"(r) : "f"(lo), "f"(hi)); return r;
}
__device__ __forceinline__ u64 bc2(float v) { return pk2(v, v); }
__device__ __forceinline__ void fma2(u64& d, u64 a, u64 b) {
    asm("fma.rn.f32x2 %0, %1, %2, %0;" : "+l"(d) : "l"(a), "l"(b));
}
__device__ __forceinline__ float2 up2(u64 v) {
    float2 f; asm("mov.b64 {%0, %1}, %2;" : "=f"(f.x), "=f"(f.y) : "l"(v)); return f;
}

// ---------------- bf16 split + mma + ldmatrix helpers ----------------
__device__ __forceinline__ void bsplit(float x, unsigned short* h, unsigned short* l) {
    __nv_bfloat16 hh = __float2bfloat16_rn(x);
    *h = __bfloat16_as_ushort(hh);
    *l = __bfloat16_as_ushort(__float2bfloat16_rn(x - __bfloat162float(hh)));
}
__device__ __forceinline__ void mma_bf16(float* d, const u32* a, u32 b0, u32 b1) {
    asm("mma.sync.aligned.m16n8k16.row.col.f32.bf16.bf16.f32 "
        "{%0,%1,%2,%3},{%4,%5,%6,%7},{%8,%9},{%0,%1,%2,%3};"
        : "+f"(d[0]), "+f"(d[1]), "+f"(d[2]), "+f"(d[3])
        : "r"(a[0]), "r"(a[1]), "r"(a[2]), "r"(a[3]), "r"(b0), "r"(b1));
}
__device__ __forceinline__ void ldsm4(u32* r, u32 addr) {
    asm volatile("ldmatrix.sync.aligned.m8n8.x4.shared.b16 {%0,%1,%2,%3}, [%4];"
                 : "=r"(r[0]), "=r"(r[1]), "=r"(r[2]), "=r"(r[3]) : "r"(addr));
}
__device__ __forceinline__ u32 smem_u32(const void* p) {
    u32 a; asm("{ .reg .u64 t; cvta.to.shared.u64 t, %1; cvt.u32.u64 %0, t; }" : "=r"(a) : "l"(p));
    return a;
}

// ---------------- scratch ----------------
__device__ __nv_bfloat16 g_h1h[(size_t)NSAMP * 16384];  // [n][256 pos][64 ic]
__device__ __nv_bfloat16 g_h1l[(size_t)NSAMP * 16384];
__device__ __nv_bfloat16 g_h2h[(size_t)NSAMP * 16384];  // [n][128 pp][128 ic]
__device__ __nv_bfloat16 g_h2l[(size_t)NSAMP * 16384];
__device__ uint4 g_w2ph[5120], g_w2pl[5120];            // prepacked A frags conv2
__device__ uint4 g_w3ph[12288], g_w3pl[12288];          // prepacked A frags conv3
__device__ float g_feat[(size_t)NSAMP * 256];
__device__ float g_z[(size_t)NSAMP * 128];
__device__ float g_sq[NSAMP];
__device__ float g_fcwT[256 * 128];

// ---------------- weight prep: fragment-order packing ----------------
__global__ void k_prep_w2(const float* __restrict__ w2) {
    int idx = blockIdx.x * blockDim.x + threadIdx.x;
    if (idx >= 5120) return;
    int lane = idx & 31, mt = (idx >> 5) & 7, kt = (idx >> 8) & 3, s = idx >> 10;
    int g = lane >> 2, tc = lane & 3;
    int m = mt * 16 + g, c = kt * 16 + 2 * tc;
    int rows[4] = {m, m + 8, m, m + 8};
    int cols[4] = {c, c, c + 8, c + 8};
    u32 hq[4], lq[4];
#pragma unroll
    for (int i = 0; i < 4; i++) {
        unsigned short h0, l0, h1, l1;
        bsplit(w2[rows[i] * 320 + cols[i] * 5 + s], &h0, &l0);
        bsplit(w2[rows[i] * 320 + (cols[i] + 1) * 5 + s], &h1, &l1);
        hq[i] = (u32)h0 | ((u32)h1 << 16);
        lq[i] = (u32)l0 | ((u32)l1 << 16);
    }
    g_w2ph[idx] = make_uint4(hq[0], hq[1], hq[2], hq[3]);
    g_w2pl[idx] = make_uint4(lq[0], lq[1], lq[2], lq[3]);
}
__global__ void k_prep_w3(const float* __restrict__ w3) {
    int idx = blockIdx.x * blockDim.x + threadIdx.x;
    if (idx >= 12288) return;
    int lane = idx & 31, mt = (idx >> 5) & 15, kt = (idx >> 9) & 7, s = idx >> 12;
    int g = lane >> 2, tc = lane & 3;
    int m = mt * 16 + g, c = kt * 16 + 2 * tc;
    int rows[4] = {m, m + 8, m, m + 8};
    int cols[4] = {c, c, c + 8, c + 8};
    u32 hq[4], lq[4];
#pragma unroll
    for (int i = 0; i < 4; i++) {
        unsigned short h0, l0, h1, l1;
        bsplit(w3[rows[i] * 384 + cols[i] * 3 + s], &h0, &l0);
        bsplit(w3[rows[i] * 384 + (cols[i] + 1) * 3 + s], &h1, &l1);
        hq[i] = (u32)h0 | ((u32)h1 << 16);
        lq[i] = (u32)l0 | ((u32)l1 << 16);
    }
    g_w3ph[idx] = make_uint4(hq[0], hq[1], hq[2], hq[3]);
    g_w3pl[idx] = make_uint4(lq[0], lq[1], lq[2], lq[3]);
}

// ---------------- conv1 (FFMA2) -> split-bf16, coalesced via smem staging ----------------
#define C1_SMEM 73728
__global__ void k_conv1(const float* __restrict__ x,
                        const float* __restrict__ w,
                        const float* __restrict__ b) {
    extern __shared__ __align__(16) float c1sm[];
    float* wsT = c1sm;            // [100*66]
    float* xs  = c1sm + 6600;     // [612]
    const int n = blockIdx.x;
    const int tid = threadIdx.x;  // 256
    const float* xn = x + (size_t)n * 512;

    for (int i = tid; i < 611; i += 256) {
        int j = i - 49;
        xs[i] = (j >= 0 && j < 512) ? xn[j] : 0.f;
    }
    for (int i = tid; i < 6400; i += 256) {
        int ol = i / 100, k = i % 100;
        wsT[k * 66 + ol] = w[i];
    }
    __syncthreads();

    const int pp = tid;
    u32 hpk[32], lpk[32];  // oc pairs

#pragma unroll
    for (int og = 0; og < 64; og += 16) {
        u64 acc0[8], acc1[8];
#pragma unroll
        for (int op = 0; op < 8; op++) {
            u64 bb = pk2(b[og + 2 * op], b[og + 2 * op + 1]);
            acc0[op] = bb; acc1[op] = bb;
        }
        float xa = xs[2 * pp];
#pragma unroll 4
        for (int k = 0; k < 100; k++) {
            float xb = xs[2 * pp + k + 1];
            u64 xap = bc2(xa), xbp = bc2(xb);
            const float* wrow = wsT + k * 66 + og;
#pragma unroll
            for (int op = 0; op < 8; op++) {
                u64 wp = *reinterpret_cast<const u64*>(wrow + 2 * op);
                fma2(acc0[op], wp, xap);
                fma2(acc1[op], wp, xbp);
            }
            xa = xb;
        }
#pragma unroll
        for (int op = 0; op < 8; op++) {
            float2 a0 = up2(acc0[op]), a1 = up2(acc1[op]);
            float v0 = fmaxf(fmaxf(a0.x, a1.x), 0.f);
            float v1 = fmaxf(fmaxf(a0.y, a1.y), 0.f);
            unsigned short h0, l0, h1, l1;
            bsplit(v0, &h0, &l0); bsplit(v1, &h1, &l1);
            hpk[og / 2 + op] = (u32)h0 | ((u32)h1 << 16);
            lpk[og / 2 + op] = (u32)l0 | ((u32)l1 << 16);
        }
    }
    __syncthreads();  // done with wsT/xs; reuse smem for staging

    // stage [256 pos][64 oc] with 144B row stride
    char* Sh = (char*)c1sm;
    char* Sl = (char*)c1sm + 36864;
#pragma unroll
    for (int blk = 0; blk < 8; blk++) {
        *(uint4*)(Sh + pp * 144 + blk * 16) =
            make_uint4(hpk[4 * blk], hpk[4 * blk + 1], hpk[4 * blk + 2], hpk[4 * blk + 3]);
        *(uint4*)(Sl + pp * 144 + blk * 16) =
            make_uint4(lpk[4 * blk], lpk[4 * blk + 1], lpk[4 * blk + 2], lpk[4 * blk + 3]);
    }
    __syncthreads();
    char* dh = (char*)g_h1h + (size_t)n * 32768;
    char* dl = (char*)g_h1l + (size_t)n * 32768;
    for (int i = tid; i < 2048; i += 256) {
        int r = i >> 3, blk = i & 7;
        *(uint4*)(dh + r * 128 + blk * 16) = *(const uint4*)(Sh + r * 144 + blk * 16);
        *(uint4*)(dl + r * 128 + blk * 16) = *(const uint4*)(Sl + r * 144 + blk * 16);
    }
}

// ---------------- conv2 (mma.sync + ldmatrix) ----------------
// X smem [260 rows][72 elems] hi+lo; row r = input pos r-2
#define C2_SMEM (2 * 260 * 72 * 2)
__global__ void __launch_bounds__(512) k_conv2(const float* __restrict__ b2) {
    extern __shared__ __align__(16) __nv_bfloat16 sm[];
    __nv_bfloat16* Xh = sm;
    __nv_bfloat16* Xl = sm + 18720;
    const int n = blockIdx.x;
    const int tid = threadIdx.x;  // 512
    const int lane = tid & 31, wp = tid >> 5;

    // zero pad rows 0,1,258,259 (cols 0..63)
    for (int i = tid; i < 128; i += 512) {
        int rr = i >> 5;
        int row = (rr < 2) ? rr : 256 + rr;
        int cw = i & 31;
        ((u32*)(Xh + row * 72))[cw] = 0u;
        ((u32*)(Xl + row * 72))[cw] = 0u;
    }
    {
        const char* srch = (const char*)g_h1h + (size_t)n * 32768;
        const char* srcl = (const char*)g_h1l + (size_t)n * 32768;
        for (int i = tid; i < 2048; i += 512) {
            int r = i >> 3, blk = i & 7;
            *(uint4*)((char*)Xh + (r + 2) * 144 + blk * 16) = *(const uint4*)(srch + r * 128 + blk * 16);
            *(uint4*)((char*)Xl + (r + 2) * 144 + blk * 16) = *(const uint4*)(srcl + r * 128 + blk * 16);
        }
    }
    __syncthreads();

    // warp tiling: mp=m-pair(0..3), nh=n-half, jb=j-half
    const int mp = wp >> 2, nh = (wp >> 1) & 1, jb = wp & 1;
    const int n0 = nh * 128, jbase = jb * 8;
    const int q = lane >> 3, rr = lane & 7;
    const u32 xhA = smem_u32(Xh);
    const u32 xlOff = 18720 * 2;
    const int rowq = n0 + 8 * jbase + 8 * (q >> 1) + rr;

    float acc[2][8][4];
#pragma unroll
    for (int m = 0; m < 2; m++)
#pragma unroll
        for (int j = 0; j < 8; j++) { acc[m][j][0] = acc[m][j][1] = acc[m][j][2] = acc[m][j][3] = 0.f; }

    for (int s = 0; s < 5; s++) {
        const u32 rbyte = (u32)(rowq + s) * 144u;
#pragma unroll
        for (int kt = 0; kt < 4; kt++) {
            const u32 colb = (u32)(kt * 32 + (q & 1) * 16);
            const uint4 AhA = g_w2ph[(s * 4 + kt) * 256 + (2 * mp) * 32 + lane];
            const uint4 AlA = g_w2pl[(s * 4 + kt) * 256 + (2 * mp) * 32 + lane];
            const uint4 AhB = g_w2ph[(s * 4 + kt) * 256 + (2 * mp + 1) * 32 + lane];
            const uint4 AlB = g_w2pl[(s * 4 + kt) * 256 + (2 * mp + 1) * 32 + lane];
#pragma unroll
            for (int jp = 0; jp < 4; jp++) {
                u32 ad = xhA + rbyte + (u32)(jp * 2304) + colb;  // 16 rows * 144B
                u32 Bh[4], Bl[4];
                ldsm4(Bh, ad);
                ldsm4(Bl, ad + xlOff);
                mma_bf16(acc[0][2 * jp],     (const u32*)&AhA, Bh[0], Bh[1]);
                mma_bf16(acc[0][2 * jp],     (const u32*)&AhA, Bl[0], Bl[1]);
                mma_bf16(acc[0][2 * jp],     (const u32*)&AlA, Bh[0], Bh[1]);
                mma_bf16(acc[0][2 * jp + 1], (const u32*)&AhA, Bh[2], Bh[3]);
                mma_bf16(acc[0][2 * jp + 1], (const u32*)&AhA, Bl[2], Bl[3]);
                mma_bf16(acc[0][2 * jp + 1], (const u32*)&AlA, Bh[2], Bh[3]);
                mma_bf16(acc[1][2 * jp],     (const u32*)&AhB, Bh[0], Bh[1]);
                mma_bf16(acc[1][2 * jp],     (const u32*)&AhB, Bl[0], Bl[1]);
                mma_bf16(acc[1][2 * jp],     (const u32*)&AlB, Bh[0], Bh[1]);
                mma_bf16(acc[1][2 * jp + 1], (const u32*)&AhB, Bh[2], Bh[3]);
                mma_bf16(acc[1][2 * jp + 1], (const u32*)&AhB, Bl[2], Bl[3]);
                mma_bf16(acc[1][2 * jp + 1], (const u32*)&AlB, Bh[2], Bh[3]);
            }
        }
    }
    __syncthreads();  // all X reads done; reuse smem as staging

    // epilogue: relu+pool+bias -> stage [128 pp][136] hi/lo
    unsigned short* Sh = (unsigned short*)sm;
    unsigned short* Sl = (unsigned short*)(sm + 18720);
    const int g2 = lane >> 2, tc = lane & 3;
#pragma unroll
    for (int m = 0; m < 2; m++) {
        const int m0 = mp * 32 + m * 16;
        const float bi0 = b2[m0 + g2], bi1 = b2[m0 + g2 + 8];
#pragma unroll
        for (int jl = 0; jl < 8; jl++) {
            int pp = n0 / 2 + 4 * (jbase + jl) + tc;
            float v0 = fmaxf(fmaxf(acc[m][jl][0] + bi0, acc[m][jl][1] + bi0), 0.f);
            float v1 = fmaxf(fmaxf(acc[m][jl][2] + bi1, acc[m][jl][3] + bi1), 0.f);
            unsigned short h, l;
            bsplit(v0, &h, &l);
            Sh[pp * 136 + m0 + g2] = h; Sl[pp * 136 + m0 + g2] = l;
            bsplit(v1, &h, &l);
            Sh[pp * 136 + m0 + g2 + 8] = h; Sl[pp * 136 + m0 + g2 + 8] = l;
        }
    }
    __syncthreads();
    char* dh = (char*)g_h2h + (size_t)n * 32768;
    char* dl = (char*)g_h2l + (size_t)n * 32768;
    for (int i = tid; i < 2048; i += 512) {
        int r = i >> 4, blk = i & 15;
        *(uint4*)(dh + r * 256 + blk * 16) = *(const uint4*)((char*)Sh + r * 272 + blk * 16);
        *(uint4*)(dl + r * 256 + blk * 16) = *(const uint4*)((char*)Sl + r * 272 + blk * 16);
    }
}

// ---------------- conv3 (mma.sync + ldmatrix) + pool + mean ----------------
// X smem [130 rows][136 elems]; row r = input pos r-1
#define C3_SMEM (2 * 130 * 136 * 2)
__global__ void __launch_bounds__(512) k_conv3(const float* __restrict__ b3) {
    extern __shared__ __align__(16) __nv_bfloat16 sm3[];
    __nv_bfloat16* Xh = sm3;
    __nv_bfloat16* Xl = sm3 + 17680;
    const int n = blockIdx.x;
    const int tid = threadIdx.x;  // 512
    const int lane = tid & 31, wp = tid >> 5;

    for (int i = tid; i < 128; i += 512) {
        int row = (i >> 6) ? 129 : 0;
        int cw = i & 63;
        ((u32*)(Xh + row * 136))[cw] = 0u;
        ((u32*)(Xl + row * 136))[cw] = 0u;
    }
    {
        const char* srch = (const char*)g_h2h + (size_t)n * 32768;
        const char* srcl = (const char*)g_h2l + (size_t)n * 32768;
        for (int i = tid; i < 2048; i += 512) {
            int r = i >> 4, blk = i & 15;
            *(uint4*)((char*)Xh + (r + 1) * 272 + blk * 16) = *(const uint4*)(srch + r * 256 + blk * 16);
            *(uint4*)((char*)Xl + (r + 1) * 272 + blk * 16) = *(const uint4*)(srcl + r * 256 + blk * 16);
        }
    }
    __syncthreads();

    const int mp = wp >> 1, jb = wp & 1;
    const int jbase = jb * 8;
    const int q = lane >> 3, rr = lane & 7;
    const u32 xhA = smem_u32(Xh);
    const u32 xlOff = 17680 * 2;
    const int rowq = 8 * jbase + 8 * (q >> 1) + rr;

    float acc[2][8][4];
#pragma unroll
    for (int m = 0; m < 2; m++)
#pragma unroll
        for (int j = 0; j < 8; j++) { acc[m][j][0] = acc[m][j][1] = acc[m][j][2] = acc[m][j][3] = 0.f; }

    for (int s = 0; s < 3; s++) {
        const u32 rbyte = (u32)(rowq + s) * 272u;
#pragma unroll
        for (int kt = 0; kt < 8; kt++) {
            const u32 colb = (u32)(kt * 32 + (q & 1) * 16);
            const uint4 AhA = g_w3ph[(s * 8 + kt) * 512 + (2 * mp) * 32 + lane];
            const uint4 AlA = g_w3pl[(s * 8 + kt) * 512 + (2 * mp) * 32 + lane];
            const uint4 AhB = g_w3ph[(s * 8 + kt) * 512 + (2 * mp + 1) * 32 + lane];
            const uint4 AlB = g_w3pl[(s * 8 + kt) * 512 + (2 * mp + 1) * 32 + lane];
#pragma unroll
            for (int jp = 0; jp < 4; jp++) {
                u32 ad = xhA + rbyte + (u32)(jp * 4352) + colb;  // 16 rows * 272B
                u32 Bh[4], Bl[4];
                ldsm4(Bh, ad);
                ldsm4(Bl, ad + xlOff);
                mma_bf16(acc[0][2 * jp],     (const u32*)&AhA, Bh[0], Bh[1]);
                mma_bf16(acc[0][2 * jp],     (const u32*)&AhA, Bl[0], Bl[1]);
                mma_bf16(acc[0][2 * jp],     (const u32*)&AlA, Bh[0], Bh[1]);
                mma_bf16(acc[0][2 * jp + 1], (const u32*)&AhA, Bh[2], Bh[3]);
                mma_bf16(acc[0][2 * jp + 1], (const u32*)&AhA, Bl[2], Bl[3]);
                mma_bf16(acc[0][2 * jp + 1], (const u32*)&AlA, Bh[2], Bh[3]);
                mma_bf16(acc[1][2 * jp],     (const u32*)&AhB, Bh[0], Bh[1]);
                mma_bf16(acc[1][2 * jp],     (const u32*)&AhB, Bl[0], Bl[1]);
                mma_bf16(acc[1][2 * jp],     (const u32*)&AlB, Bh[0], Bh[1]);
                mma_bf16(acc[1][2 * jp + 1], (const u32*)&AhB, Bh[2], Bh[3]);
                mma_bf16(acc[1][2 * jp + 1], (const u32*)&AhB, Bl[2], Bl[3]);
                mma_bf16(acc[1][2 * jp + 1], (const u32*)&AlB, Bh[2], Bh[3]);
            }
        }
    }
    __syncthreads();  // X reads done; reuse smem for partials

    float* part = (float*)sm3;  // [256 oc][2 j-halves]
    const int g2 = lane >> 2, tc = lane & 3;
#pragma unroll
    for (int m = 0; m < 2; m++) {
        const int m0 = mp * 32 + m * 16;
        const float bi0 = b3[m0 + g2], bi1 = b3[m0 + g2 + 8];
        float s0 = 0.f, s1 = 0.f;
#pragma unroll
        for (int jl = 0; jl < 8; jl++) {
            float a0 = fmaxf(acc[m][jl][0] + bi0, 0.f);
            float a1 = fmaxf(acc[m][jl][1] + bi0, 0.f);
            s0 += fmaxf(a0, a1);
            float c0 = fmaxf(acc[m][jl][2] + bi1, 0.f);
            float c1 = fmaxf(acc[m][jl][3] + bi1, 0.f);
            s1 += fmaxf(c0, c1);
        }
        s0 += __shfl_xor_sync(0xFFFFFFFFu, s0, 1);
        s0 += __shfl_xor_sync(0xFFFFFFFFu, s0, 2);
        s1 += __shfl_xor_sync(0xFFFFFFFFu, s1, 1);
        s1 += __shfl_xor_sync(0xFFFFFFFFu, s1, 2);
        if (tc == 0) {
            part[(m0 + g2) * 2 + jb]     = s0;
            part[(m0 + g2 + 8) * 2 + jb] = s1;
        }
    }
    __syncthreads();
    if (tid < 256) {
        g_feat[(size_t)n * 256 + tid] = (part[2 * tid] + part[2 * tid + 1]) * (1.f / 64.f);
    }
}

// ---------------- fc weight transpose ----------------
__global__ void k_fcT(const float* __restrict__ fcw) {
    int idx = blockIdx.x * blockDim.x + threadIdx.x;
    if (idx < 128 * 256) {
        int j = idx / 256, k = idx % 256;
        g_fcwT[k * 128 + j] = fcw[idx];
    }
}

// ---------------- fc + relu + bn ----------------
__global__ void k_fc(const float* __restrict__ fcb, const float* __restrict__ gamma,
                     const float* __restrict__ beta, const float* __restrict__ mean,
                     const float* __restrict__ var) {
    const int n = blockIdx.x;
    const int j = threadIdx.x;  // 128
    __shared__ float fs[256];
    __shared__ float ps[4];
    fs[j]       = g_feat[(size_t)n * 256 + j];
    fs[j + 128] = g_feat[(size_t)n * 256 + 128 + j];
    __syncthreads();
    float acc = fcb[j];
#pragma unroll 8
    for (int k = 0; k < 256; k++) acc = fmaf(fs[k], g_fcwT[k * 128 + j], acc);
    acc = fmaxf(acc, 0.f);
    float z = gamma[j] * (acc - mean[j]) * rsqrtf(var[j] + 1e-5f) + beta[j];
    g_z[(size_t)n * 128 + j] = z;
    float s = z * z;
#pragma unroll
    for (int off = 16; off; off >>= 1) s += __shfl_xor_sync(0xFFFFFFFFu, s, off);
    if ((j & 31) == 0) ps[j >> 5] = s;
    __syncthreads();
    if (j == 0) g_sq[n] = ps[0] + ps[1] + ps[2] + ps[3];
}

// ---------------- pairwise output (FFMA2) ----------------
#define PAIR_SMEM ((64 * 130 + 128 * 66) * sizeof(float))
__global__ void k_pair(const int* __restrict__ info, float* __restrict__ out) {
    extern __shared__ float pbuf[];
    float* As = pbuf;
    float* Bs = pbuf + 64 * 130;
    const int jb = blockIdx.x * 64;
    const int ib = blockIdx.y * 64;
    const int tid = threadIdx.x;  // 256

    for (int idx = tid; idx < 64 * 128; idx += 256) {
        int r = idx >> 7, k = idx & 127;
        As[r * 130 + k] = g_z[(size_t)(ib + r) * 128 + k];
        Bs[k * 66 + r]  = g_z[(size_t)(jb + r) * 128 + k];
    }
    __syncthreads();

    const int tx = tid & 15, ty = tid >> 4;
    u64 c[4][2];
#pragma unroll
    for (int r = 0; r < 4; r++) { c[r][0] = 0ull; c[r][1] = 0ull; }
    for (int k = 0; k < 128; k++) {
        u64 bp0 = *reinterpret_cast<const u64*>(Bs + k * 66 + 4 * tx);
        u64 bp1 = *reinterpret_cast<const u64*>(Bs + k * 66 + 4 * tx + 2);
#pragma unroll
        for (int r = 0; r < 4; r++) {
            u64 ap = bc2(As[(ty * 4 + r) * 130 + k]);
            fma2(c[r][0], ap, bp0);
            fma2(c[r][1], ap, bp1);
        }
    }

    float sqi[4], sqj[4];
    int wti[4], wtj[4], gi[4], gj[4];
#pragma unroll
    for (int r = 0; r < 4; r++) {
        int i = ib + ty * 4 + r;
        sqi[r] = g_sq[i]; wti[r] = info[2 * i]; gi[r] = info[2 * i + 1];
    }
#pragma unroll
    for (int q = 0; q < 4; q++) {
        int j = jb + tx * 4 + q;
        sqj[q] = g_sq[j]; wtj[q] = info[2 * j]; gj[q] = info[2 * j + 1];
    }

#pragma unroll
    for (int r = 0; r < 4; r++) {
        int i = ib + ty * 4 + r;
        float cc[4];
        float2 c0 = up2(c[r][0]), c1 = up2(c[r][1]);
        cc[0] = c0.x; cc[1] = c0.y; cc[2] = c1.x; cc[3] = c1.y;
        float4 v; float res[4];
#pragma unroll
        for (int q = 0; q < 4; q++) {
            int j = jb + tx * 4 + q;
            float d2 = sqi[r] + sqj[q] - 2.f * cc[q];
            float d = sqrtf(fmaxf(d2, 0.f));
            bool y = (wti[r] == wtj[q]) && (gi[r] == 1) && (gj[q] == 1);
            float cl = y ? d : fmaxf(1.f - d, 0.f);
            res[q] = (i == j) ? 0.f : cl;
        }
        v.x = res[0]; v.y = res[1]; v.z = res[2]; v.w = res[3];
        *reinterpret_cast<float4*>(out + (size_t)i * 4096 + jb + tx * 4) = v;
    }
}

// ---------------- launch ----------------
extern "C" void kernel_launch(void* const* d_in, const int* in_sizes, int n_in,
                              void* d_out, int out_size) {
    const float* samples = (const float*)d_in[0];
    const int*   info    = (const int*)d_in[1];
    const float* w1  = (const float*)d_in[2];
    const float* b1  = (const float*)d_in[3];
    const float* w2  = (const float*)d_in[4];
    const float* b2  = (const float*)d_in[5];
    const float* w3  = (const float*)d_in[6];
    const float* b3  = (const float*)d_in[7];
    const float* fcw = (const float*)d_in[8];
    const float* fcb = (const float*)d_in[9];
    const float* gam = (const float*)d_in[10];
    const float* bet = (const float*)d_in[11];
    const float* bmu = (const float*)d_in[12];
    const float* bva = (const float*)d_in[13];
    float* out = (float*)d_out;

    cudaFuncSetAttribute(k_conv1, cudaFuncAttributeMaxDynamicSharedMemorySize, C1_SMEM);
    cudaFuncSetAttribute(k_conv2, cudaFuncAttributeMaxDynamicSharedMemorySize, C2_SMEM);
    cudaFuncSetAttribute(k_conv3, cudaFuncAttributeMaxDynamicSharedMemorySize, C3_SMEM);
    cudaFuncSetAttribute(k_pair,  cudaFuncAttributeMaxDynamicSharedMemorySize, (int)PAIR_SMEM);

    k_prep_w2<<<20, 256>>>(w2);
    k_prep_w3<<<48, 256>>>(w3);
    k_fcT<<<64, 512>>>(fcw);
    k_conv1<<<NSAMP, 256, C1_SMEM>>>(samples, w1, b1);
    k_conv2<<<NSAMP, 512, C2_SMEM>>>(b2);
    k_conv3<<<NSAMP, 512, C3_SMEM>>>(b3);
    k_fc<<<NSAMP, 128>>>(fcb, gam, bet, bmu, bva);
    k_pair<<<dim3(64, 64), 256, PAIR_SMEM>>>(info, out);
}

// round 9
// speedup vs baseline: 4.3071x; 1.0589x over previous
#include <cuda_runtime.h>
#include <cuda_bf16.h>
#include <cstdint>

#define NSAMP 4096
typedef unsigned long long u64;
typedef unsigned int u32;
typedef unsigned short u16;

// ---------------- bf16 split + mma + ldmatrix helpers ----------------
__device__ __forceinline__ void bsplit(float x, u16* h, u16* l) {
    __nv_bfloat16 hh = __float2bfloat16_rn(x);
    *h = __bfloat16_as_ushort(hh);
    *l = __bfloat16_as_ushort(__float2bfloat16_rn(x - __bfloat162float(hh)));
}
__device__ __forceinline__ void mma_bf16(float* d, const u32* a, u32 b0, u32 b1) {
    asm("mma.sync.aligned.m16n8k16.row.col.f32.bf16.bf16.f32 "
        "{%0,%1,%2,%3},{%4,%5,%6,%7},{%8,%9},{%0,%1,%2,%3};"
        : "+f"(d[0]), "+f"(d[1]), "+f"(d[2]), "+f"(d[3])
        : "r"(a[0]), "r"(a[1]), "r"(a[2]), "r"(a[3]), "r"(b0), "r"(b1));
}
__device__ __forceinline__ void ldsm4(u32* r, u32 addr) {
    asm volatile("ldmatrix.sync.aligned.m8n8.x4.shared.b16 {%0,%1,%2,%3}, [%4];"
                 : "=r"(r[0]), "=r"(r[1]), "=r"(r[2]), "=r"(r[3]) : "r"(addr));
}
__device__ __forceinline__ u32 smem_u32(const void* p) {
    u32 a; asm("{ .reg .u64 t; cvta.to.shared.u64 t, %1; cvt.u32.u64 %0, t; }" : "=r"(a) : "l"(p));
    return a;
}

// ---------------- scratch ----------------
__device__ __nv_bfloat16 g_h1h[(size_t)NSAMP * 16384];  // [n][256 pos][64 ic]
__device__ __nv_bfloat16 g_h1l[(size_t)NSAMP * 16384];
__device__ __nv_bfloat16 g_h2h[(size_t)NSAMP * 16384];  // [n][128 pp][128 ic]
__device__ __nv_bfloat16 g_h2l[(size_t)NSAMP * 16384];
__device__ uint4 g_w1ph[896],  g_w1pl[896];             // conv1 A frags (4 mt x 7 kt)
__device__ uint4 g_w2ph[5120], g_w2pl[5120];
__device__ uint4 g_w3ph[12288], g_w3pl[12288];
__device__ float g_feat[(size_t)NSAMP * 256];
__device__ float g_z[(size_t)NSAMP * 128];
__device__ u16   g_zh[(size_t)NSAMP * 128];
__device__ u16   g_zl[(size_t)NSAMP * 128];
__device__ float g_sq[NSAMP];
__device__ float g_fcwT[256 * 128];

// ---------------- weight prep: fragment-order packing ----------------
__global__ void k_prep_w1(const float* __restrict__ w1) {
    int idx = blockIdx.x * blockDim.x + threadIdx.x;
    if (idx >= 896) return;
    int lane = idx & 31, mt = (idx >> 5) & 3, kt = idx >> 7;  // kt 0..6
    int g = lane >> 2, tc = lane & 3;
    int m = mt * 16 + g, c = kt * 16 + 2 * tc;
    int rows[4] = {m, m + 8, m, m + 8};
    int cols[4] = {c, c, c + 8, c + 8};
    u32 hq[4], lq[4];
#pragma unroll
    for (int i = 0; i < 4; i++) {
        u16 h0 = 0, l0 = 0, h1 = 0, l1 = 0;
        if (cols[i] < 100)     bsplit(w1[rows[i] * 100 + cols[i]], &h0, &l0);
        if (cols[i] + 1 < 100) bsplit(w1[rows[i] * 100 + cols[i] + 1], &h1, &l1);
        hq[i] = (u32)h0 | ((u32)h1 << 16);
        lq[i] = (u32)l0 | ((u32)l1 << 16);
    }
    g_w1ph[idx] = make_uint4(hq[0], hq[1], hq[2], hq[3]);
    g_w1pl[idx] = make_uint4(lq[0], lq[1], lq[2], lq[3]);
}
__global__ void k_prep_w2(const float* __restrict__ w2) {
    int idx = blockIdx.x * blockDim.x + threadIdx.x;
    if (idx >= 5120) return;
    int lane = idx & 31, mt = (idx >> 5) & 7, kt = (idx >> 8) & 3, s = idx >> 10;
    int g = lane >> 2, tc = lane & 3;
    int m = mt * 16 + g, c = kt * 16 + 2 * tc;
    int rows[4] = {m, m + 8, m, m + 8};
    int cols[4] = {c, c, c + 8, c + 8};
    u32 hq[4], lq[4];
#pragma unroll
    for (int i = 0; i < 4; i++) {
        u16 h0, l0, h1, l1;
        bsplit(w2[rows[i] * 320 + cols[i] * 5 + s], &h0, &l0);
        bsplit(w2[rows[i] * 320 + (cols[i] + 1) * 5 + s], &h1, &l1);
        hq[i] = (u32)h0 | ((u32)h1 << 16);
        lq[i] = (u32)l0 | ((u32)l1 << 16);
    }
    g_w2ph[idx] = make_uint4(hq[0], hq[1], hq[2], hq[3]);
    g_w2pl[idx] = make_uint4(lq[0], lq[1], lq[2], lq[3]);
}
__global__ void k_prep_w3(const float* __restrict__ w3) {
    int idx = blockIdx.x * blockDim.x + threadIdx.x;
    if (idx >= 12288) return;
    int lane = idx & 31, mt = (idx >> 5) & 15, kt = (idx >> 9) & 7, s = idx >> 12;
    int g = lane >> 2, tc = lane & 3;
    int m = mt * 16 + g, c = kt * 16 + 2 * tc;
    int rows[4] = {m, m + 8, m, m + 8};
    int cols[4] = {c, c, c + 8, c + 8};
    u32 hq[4], lq[4];
#pragma unroll
    for (int i = 0; i < 4; i++) {
        u16 h0, l0, h1, l1;
        bsplit(w3[rows[i] * 384 + cols[i] * 3 + s], &h0, &l0);
        bsplit(w3[rows[i] * 384 + (cols[i] + 1) * 3 + s], &h1, &l1);
        hq[i] = (u32)h0 | ((u32)h1 << 16);
        lq[i] = (u32)l0 | ((u32)l1 << 16);
    }
    g_w3ph[idx] = make_uint4(hq[0], hq[1], hq[2], hq[3]);
    g_w3pl[idx] = make_uint4(lq[0], lq[1], lq[2], lq[3]);
}

// ---------------- conv1 (mma.sync, im2col-by-shift) ----------------
// B[p][k] = x[P0 + p + k - 49]; tile [256 rows][120 cols], stride 240B
#define C1_BH 0
#define C1_BL 61440
#define C1_XH 122880
#define C1_XL 123616
#define C1T_SMEM (123616 + 736)
__global__ void __launch_bounds__(512) k_conv1(const float* __restrict__ x,
                                               const float* __restrict__ b1) {
    extern __shared__ __align__(16) char c1sm[];
    u16* Bh = (u16*)c1sm;
    u16* Bl = (u16*)(c1sm + C1_BL);
    u16* xh_s = (u16*)(c1sm + C1_XH);
    u16* xl_s = (u16*)(c1sm + C1_XL);
    const int n = blockIdx.x;
    const int P0 = blockIdx.y * 256;
    const int tid = threadIdx.x;  // 512
    const int lane = tid & 31, wp = tid >> 5;
    const float* xn = x + (size_t)n * 512;

    // stage split x[P0-49 .. P0+305]
    for (int i = tid; i < 355; i += 512) {
        int j = P0 - 49 + i;
        float v = (j >= 0 && j < 512) ? xn[j] : 0.f;
        u16 h, l; bsplit(v, &h, &l);
        xh_s[i] = h; xl_s[i] = l;
    }
    __syncthreads();
    // build B tiles (cols 0..99 data, 100..119 zero)
    for (int idx = tid; idx < 256 * 60; idx += 512) {
        int row = idx / 60, kp = idx % 60;
        u32 vh = 0, vl = 0;
        if (kp < 50) {
            int base = row + 2 * kp;
            vh = (u32)xh_s[base] | ((u32)xh_s[base + 1] << 16);
            vl = (u32)xl_s[base] | ((u32)xl_s[base + 1] << 16);
        }
        *(u32*)(Bh + row * 120 + 2 * kp) = vh;
        *(u32*)(Bl + row * 120 + 2 * kp) = vl;
    }
    __syncthreads();

    const int mt = wp >> 2, nq = wp & 3;
    const int n0 = nq * 64;
    const int q = lane >> 3, rr = lane & 7;
    const u32 bA = smem_u32(Bh);
    const int rowq = n0 + 8 * (q >> 1) + rr;

    float acc[8][4];
#pragma unroll
    for (int j = 0; j < 8; j++) { acc[j][0] = acc[j][1] = acc[j][2] = acc[j][3] = 0.f; }

#pragma unroll
    for (int kt = 0; kt < 7; kt++) {
        const u32 colb = (u32)(kt * 32 + (q & 1) * 16);
        const uint4 Ah = g_w1ph[(kt * 4 + mt) * 32 + lane];
        const uint4 Al = g_w1pl[(kt * 4 + mt) * 32 + lane];
#pragma unroll
        for (int jp = 0; jp < 4; jp++) {
            u32 ad = bA + (u32)(rowq + jp * 16) * 240u + colb;
            u32 Bh_[4], Bl_[4];
            ldsm4(Bh_, ad);
            ldsm4(Bl_, ad + C1_BL);
            mma_bf16(acc[2 * jp],     (const u32*)&Ah, Bh_[0], Bh_[1]);
            mma_bf16(acc[2 * jp],     (const u32*)&Ah, Bl_[0], Bl_[1]);
            mma_bf16(acc[2 * jp],     (const u32*)&Al, Bh_[0], Bh_[1]);
            mma_bf16(acc[2 * jp + 1], (const u32*)&Ah, Bh_[2], Bh_[3]);
            mma_bf16(acc[2 * jp + 1], (const u32*)&Ah, Bl_[2], Bl_[3]);
            mma_bf16(acc[2 * jp + 1], (const u32*)&Al, Bh_[2], Bh_[3]);
        }
    }
    __syncthreads();  // B reads done; reuse smem for staging

    // stage [128 pp][64 oc] rows (stride 144B) then coalesced copy
    u16* Sh = (u16*)c1sm;
    u16* Sl = (u16*)(c1sm + 36864);
    const int g2 = lane >> 2, tc = lane & 3;
    const float bi0 = b1[mt * 16 + g2], bi1 = b1[mt * 16 + g2 + 8];
#pragma unroll
    for (int jj = 0; jj < 8; jj++) {
        int pp = nq * 32 + 4 * jj + tc;
        float v0 = fmaxf(fmaxf(acc[jj][0] + bi0, acc[jj][1] + bi0), 0.f);
        float v1 = fmaxf(fmaxf(acc[jj][2] + bi1, acc[jj][3] + bi1), 0.f);
        u16 h, l;
        bsplit(v0, &h, &l);
        Sh[pp * 72 + mt * 16 + g2] = h; Sl[pp * 72 + mt * 16 + g2] = l;
        bsplit(v1, &h, &l);
        Sh[pp * 72 + mt * 16 + g2 + 8] = h; Sl[pp * 72 + mt * 16 + g2 + 8] = l;
    }
    __syncthreads();
    char* dh = (char*)g_h1h + (size_t)n * 32768 + (size_t)blockIdx.y * 16384;
    char* dl = (char*)g_h1l + (size_t)n * 32768 + (size_t)blockIdx.y * 16384;
    for (int i = tid; i < 1024; i += 512) {
        int r = i >> 3, blk = i & 7;
        *(uint4*)(dh + r * 128 + blk * 16) = *(const uint4*)((char*)Sh + r * 144 + blk * 16);
        *(uint4*)(dl + r * 128 + blk * 16) = *(const uint4*)((char*)Sl + r * 144 + blk * 16);
    }
}

// ---------------- conv2 (mma.sync + ldmatrix) ----------------
#define C2_SMEM (2 * 260 * 72 * 2)
__global__ void __launch_bounds__(512) k_conv2(const float* __restrict__ b2) {
    extern __shared__ __align__(16) __nv_bfloat16 sm[];
    __nv_bfloat16* Xh = sm;
    __nv_bfloat16* Xl = sm + 18720;
    const int n = blockIdx.x;
    const int tid = threadIdx.x;
    const int lane = tid & 31, wp = tid >> 5;

    for (int i = tid; i < 128; i += 512) {
        int rr = i >> 5;
        int row = (rr < 2) ? rr : 256 + rr;
        int cw = i & 31;
        ((u32*)(Xh + row * 72))[cw] = 0u;
        ((u32*)(Xl + row * 72))[cw] = 0u;
    }
    {
        const char* srch = (const char*)g_h1h + (size_t)n * 32768;
        const char* srcl = (const char*)g_h1l + (size_t)n * 32768;
        for (int i = tid; i < 2048; i += 512) {
            int r = i >> 3, blk = i & 7;
            *(uint4*)((char*)Xh + (r + 2) * 144 + blk * 16) = *(const uint4*)(srch + r * 128 + blk * 16);
            *(uint4*)((char*)Xl + (r + 2) * 144 + blk * 16) = *(const uint4*)(srcl + r * 128 + blk * 16);
        }
    }
    __syncthreads();

    const int mp = wp >> 2, nh = (wp >> 1) & 1, jb = wp & 1;
    const int n0 = nh * 128, jbase = jb * 8;
    const int q = lane >> 3, rr = lane & 7;
    const u32 xhA = smem_u32(Xh);
    const u32 xlOff = 18720 * 2;
    const int rowq = n0 + 8 * jbase + 8 * (q >> 1) + rr;

    float acc[2][8][4];
#pragma unroll
    for (int m = 0; m < 2; m++)
#pragma unroll
        for (int j = 0; j < 8; j++) { acc[m][j][0] = acc[m][j][1] = acc[m][j][2] = acc[m][j][3] = 0.f; }

    for (int s = 0; s < 5; s++) {
        const u32 rbyte = (u32)(rowq + s) * 144u;
#pragma unroll
        for (int kt = 0; kt < 4; kt++) {
            const u32 colb = (u32)(kt * 32 + (q & 1) * 16);
            const uint4 AhA = g_w2ph[(s * 4 + kt) * 256 + (2 * mp) * 32 + lane];
            const uint4 AlA = g_w2pl[(s * 4 + kt) * 256 + (2 * mp) * 32 + lane];
            const uint4 AhB = g_w2ph[(s * 4 + kt) * 256 + (2 * mp + 1) * 32 + lane];
            const uint4 AlB = g_w2pl[(s * 4 + kt) * 256 + (2 * mp + 1) * 32 + lane];
#pragma unroll
            for (int jp = 0; jp < 4; jp++) {
                u32 ad = xhA + rbyte + (u32)(jp * 2304) + colb;
                u32 Bh_[4], Bl_[4];
                ldsm4(Bh_, ad);
                ldsm4(Bl_, ad + xlOff);
                mma_bf16(acc[0][2 * jp],     (const u32*)&AhA, Bh_[0], Bh_[1]);
                mma_bf16(acc[0][2 * jp],     (const u32*)&AhA, Bl_[0], Bl_[1]);
                mma_bf16(acc[0][2 * jp],     (const u32*)&AlA, Bh_[0], Bh_[1]);
                mma_bf16(acc[0][2 * jp + 1], (const u32*)&AhA, Bh_[2], Bh_[3]);
                mma_bf16(acc[0][2 * jp + 1], (const u32*)&AhA, Bl_[2], Bl_[3]);
                mma_bf16(acc[0][2 * jp + 1], (const u32*)&AlA, Bh_[2], Bh_[3]);
                mma_bf16(acc[1][2 * jp],     (const u32*)&AhB, Bh_[0], Bh_[1]);
                mma_bf16(acc[1][2 * jp],     (const u32*)&AhB, Bl_[0], Bl_[1]);
                mma_bf16(acc[1][2 * jp],     (const u32*)&AlB, Bh_[0], Bh_[1]);
                mma_bf16(acc[1][2 * jp + 1], (const u32*)&AhB, Bh_[2], Bh_[3]);
                mma_bf16(acc[1][2 * jp + 1], (const u32*)&AhB, Bl_[2], Bl_[3]);
                mma_bf16(acc[1][2 * jp + 1], (const u32*)&AlB, Bh_[2], Bh_[3]);
            }
        }
    }
    __syncthreads();

    u16* Sh = (u16*)sm;
    u16* Sl = (u16*)(sm + 18720);
    const int g2 = lane >> 2, tc = lane & 3;
#pragma unroll
    for (int m = 0; m < 2; m++) {
        const int m0 = mp * 32 + m * 16;
        const float bi0 = b2[m0 + g2], bi1 = b2[m0 + g2 + 8];
#pragma unroll
        for (int jl = 0; jl < 8; jl++) {
            int pp = n0 / 2 + 4 * (jbase + jl) + tc;
            float v0 = fmaxf(fmaxf(acc[m][jl][0] + bi0, acc[m][jl][1] + bi0), 0.f);
            float v1 = fmaxf(fmaxf(acc[m][jl][2] + bi1, acc[m][jl][3] + bi1), 0.f);
            u16 h, l;
            bsplit(v0, &h, &l);
            Sh[pp * 136 + m0 + g2] = h; Sl[pp * 136 + m0 + g2] = l;
            bsplit(v1, &h, &l);
            Sh[pp * 136 + m0 + g2 + 8] = h; Sl[pp * 136 + m0 + g2 + 8] = l;
        }
    }
    __syncthreads();
    char* dh = (char*)g_h2h + (size_t)n * 32768;
    char* dl = (char*)g_h2l + (size_t)n * 32768;
    for (int i = tid; i < 2048; i += 512) {
        int r = i >> 4, blk = i & 15;
        *(uint4*)(dh + r * 256 + blk * 16) = *(const uint4*)((char*)Sh + r * 272 + blk * 16);
        *(uint4*)(dl + r * 256 + blk * 16) = *(const uint4*)((char*)Sl + r * 272 + blk * 16);
    }
}

// ---------------- conv3 (mma.sync + ldmatrix) + pool + mean ----------------
#define C3_SMEM (2 * 130 * 136 * 2)
__global__ void __launch_bounds__(512) k_conv3(const float* __restrict__ b3) {
    extern __shared__ __align__(16) __nv_bfloat16 sm3[];
    __nv_bfloat16* Xh = sm3;
    __nv_bfloat16* Xl = sm3 + 17680;
    const int n = blockIdx.x;
    const int tid = threadIdx.x;
    const int lane = tid & 31, wp = tid >> 5;

    for (int i = tid; i < 128; i += 512) {
        int row = (i >> 6) ? 129 : 0;
        int cw = i & 63;
        ((u32*)(Xh + row * 136))[cw] = 0u;
        ((u32*)(Xl + row * 136))[cw] = 0u;
    }
    {
        const char* srch = (const char*)g_h2h + (size_t)n * 32768;
        const char* srcl = (const char*)g_h2l + (size_t)n * 32768;
        for (int i = tid; i < 2048; i += 512) {
            int r = i >> 4, blk = i & 15;
            *(uint4*)((char*)Xh + (r + 1) * 272 + blk * 16) = *(const uint4*)(srch + r * 256 + blk * 16);
            *(uint4*)((char*)Xl + (r + 1) * 272 + blk * 16) = *(const uint4*)(srcl + r * 256 + blk * 16);
        }
    }
    __syncthreads();

    const int mp = wp >> 1, jb = wp & 1;
    const int jbase = jb * 8;
    const int q = lane >> 3, rr = lane & 7;
    const u32 xhA = smem_u32(Xh);
    const u32 xlOff = 17680 * 2;
    const int rowq = 8 * jbase + 8 * (q >> 1) + rr;

    float acc[2][8][4];
#pragma unroll
    for (int m = 0; m < 2; m++)
#pragma unroll
        for (int j = 0; j < 8; j++) { acc[m][j][0] = acc[m][j][1] = acc[m][j][2] = acc[m][j][3] = 0.f; }

    for (int s = 0; s < 3; s++) {
        const u32 rbyte = (u32)(rowq + s) * 272u;
#pragma unroll
        for (int kt = 0; kt < 8; kt++) {
            const u32 colb = (u32)(kt * 32 + (q & 1) * 16);
            const uint4 AhA = g_w3ph[(s * 8 + kt) * 512 + (2 * mp) * 32 + lane];
            const uint4 AlA = g_w3pl[(s * 8 + kt) * 512 + (2 * mp) * 32 + lane];
            const uint4 AhB = g_w3ph[(s * 8 + kt) * 512 + (2 * mp + 1) * 32 + lane];
            const uint4 AlB = g_w3pl[(s * 8 + kt) * 512 + (2 * mp + 1) * 32 + lane];
#pragma unroll
            for (int jp = 0; jp < 4; jp++) {
                u32 ad = xhA + rbyte + (u32)(jp * 4352) + colb;
                u32 Bh_[4], Bl_[4];
                ldsm4(Bh_, ad);
                ldsm4(Bl_, ad + xlOff);
                mma_bf16(acc[0][2 * jp],     (const u32*)&AhA, Bh_[0], Bh_[1]);
                mma_bf16(acc[0][2 * jp],     (const u32*)&AhA, Bl_[0], Bl_[1]);
                mma_bf16(acc[0][2 * jp],     (const u32*)&AlA, Bh_[0], Bh_[1]);
                mma_bf16(acc[0][2 * jp + 1], (const u32*)&AhA, Bh_[2], Bh_[3]);
                mma_bf16(acc[0][2 * jp + 1], (const u32*)&AhA, Bl_[2], Bl_[3]);
                mma_bf16(acc[0][2 * jp + 1], (const u32*)&AlA, Bh_[2], Bh_[3]);
                mma_bf16(acc[1][2 * jp],     (const u32*)&AhB, Bh_[0], Bh_[1]);
                mma_bf16(acc[1][2 * jp],     (const u32*)&AhB, Bl_[0], Bl_[1]);
                mma_bf16(acc[1][2 * jp],     (const u32*)&AlB, Bh_[0], Bh_[1]);
                mma_bf16(acc[1][2 * jp + 1], (const u32*)&AhB, Bh_[2], Bh_[3]);
                mma_bf16(acc[1][2 * jp + 1], (const u32*)&AhB, Bl_[2], Bl_[3]);
                mma_bf16(acc[1][2 * jp + 1], (const u32*)&AlB, Bh_[2], Bh_[3]);
            }
        }
    }
    __syncthreads();

    float* part = (float*)sm3;
    const int g2 = lane >> 2, tc = lane & 3;
#pragma unroll
    for (int m = 0; m < 2; m++) {
        const int m0 = mp * 32 + m * 16;
        const float bi0 = b3[m0 + g2], bi1 = b3[m0 + g2 + 8];
        float s0 = 0.f, s1 = 0.f;
#pragma unroll
        for (int jl = 0; jl < 8; jl++) {
            float a0 = fmaxf(acc[m][jl][0] + bi0, 0.f);
            float a1 = fmaxf(acc[m][jl][1] + bi0, 0.f);
            s0 += fmaxf(a0, a1);
            float c0 = fmaxf(acc[m][jl][2] + bi1, 0.f);
            float c1 = fmaxf(acc[m][jl][3] + bi1, 0.f);
            s1 += fmaxf(c0, c1);
        }
        s0 += __shfl_xor_sync(0xFFFFFFFFu, s0, 1);
        s0 += __shfl_xor_sync(0xFFFFFFFFu, s0, 2);
        s1 += __shfl_xor_sync(0xFFFFFFFFu, s1, 1);
        s1 += __shfl_xor_sync(0xFFFFFFFFu, s1, 2);
        if (tc == 0) {
            part[(m0 + g2) * 2 + jb]     = s0;
            part[(m0 + g2 + 8) * 2 + jb] = s1;
        }
    }
    __syncthreads();
    if (tid < 256) {
        g_feat[(size_t)n * 256 + tid] = (part[2 * tid] + part[2 * tid + 1]) * (1.f / 64.f);
    }
}

// ---------------- fc weight transpose ----------------
__global__ void k_fcT(const float* __restrict__ fcw) {
    int idx = blockIdx.x * blockDim.x + threadIdx.x;
    if (idx < 128 * 256) {
        int j = idx / 256, k = idx % 256;
        g_fcwT[k * 128 + j] = fcw[idx];
    }
}

// ---------------- fc + relu + bn (+ z split) ----------------
__global__ void k_fc(const float* __restrict__ fcb, const float* __restrict__ gamma,
                     const float* __restrict__ beta, const float* __restrict__ mean,
                     const float* __restrict__ var) {
    const int n = blockIdx.x;
    const int j = threadIdx.x;  // 128
    __shared__ float fs[256];
    __shared__ float ps[4];
    fs[j]       = g_feat[(size_t)n * 256 + j];
    fs[j + 128] = g_feat[(size_t)n * 256 + 128 + j];
    __syncthreads();
    float acc = fcb[j];
#pragma unroll 8
    for (int k = 0; k < 256; k++) acc = fmaf(fs[k], g_fcwT[k * 128 + j], acc);
    acc = fmaxf(acc, 0.f);
    float z = gamma[j] * (acc - mean[j]) * rsqrtf(var[j] + 1e-5f) + beta[j];
    g_z[(size_t)n * 128 + j] = z;
    u16 zh, zl; bsplit(z, &zh, &zl);
    g_zh[(size_t)n * 128 + j] = zh;
    g_zl[(size_t)n * 128 + j] = zl;
    float s = z * z;
#pragma unroll
    for (int off = 16; off; off >>= 1) s += __shfl_xor_sync(0xFFFFFFFFu, s, off);
    if ((j & 31) == 0) ps[j >> 5] = s;
    __syncthreads();
    if (j == 0) g_sq[n] = ps[0] + ps[1] + ps[2] + ps[3];
}

// ---------------- pairwise (mma.sync) ----------------
// 128x128 tile per CTA, 8 warps, split-bf16, stride 272B
#define PT_AOFF 34816
#define PT_SMEM (4 * 34816)
__global__ void __launch_bounds__(256) k_pair(const int* __restrict__ info, float* __restrict__ out) {
    extern __shared__ __align__(16) char psm[];
    u16* Ash = (u16*)psm;
    u16* Bsh = (u16*)(psm + 2 * PT_AOFF);
    const int ib = blockIdx.y * 128;
    const int jbb = blockIdx.x * 128;
    const int tid = threadIdx.x;  // 256
    const int lane = tid & 31, wp = tid >> 5;

    for (int i = tid; i < 2048; i += 256) {
        int r = i >> 4, c = i & 15;
        *(uint4*)((char*)Ash + r * 272 + c * 16)            = ((const uint4*)(g_zh + (size_t)(ib + r) * 128))[c];
        *(uint4*)((char*)Ash + PT_AOFF + r * 272 + c * 16)  = ((const uint4*)(g_zl + (size_t)(ib + r) * 128))[c];
        *(uint4*)((char*)Bsh + r * 272 + c * 16)            = ((const uint4*)(g_zh + (size_t)(jbb + r) * 128))[c];
        *(uint4*)((char*)Bsh + PT_AOFF + r * 272 + c * 16)  = ((const uint4*)(g_zl + (size_t)(jbb + r) * 128))[c];
    }
    __syncthreads();

    const int mh = wp >> 1, nh = wp & 1;
    const int m0base = 32 * mh, jbase = nh * 8;
    const u32 aA = smem_u32(Ash);
    const u32 bB = smem_u32(Bsh);
    // A lane addressing (ldmatrix x4 row-major A fragment)
    const int jA = lane >> 3, rA = lane & 7;
    const int arow = (jA & 1) * 8 + rA;
    const u32 acol = (u32)((jA >> 1) * 16);
    // B lane addressing (same pattern as convs)
    const int q = lane >> 3, rr = lane & 7;
    const int browq = jbase * 8 + 8 * (q >> 1) + rr;
    const u32 bcol = (u32)((q & 1) * 16);

    float acc[2][8][4];
#pragma unroll
    for (int m = 0; m < 2; m++)
#pragma unroll
        for (int j = 0; j < 8; j++) { acc[m][j][0] = acc[m][j][1] = acc[m][j][2] = acc[m][j][3] = 0.f; }

#pragma unroll
    for (int kt = 0; kt < 8; kt++) {
        u32 Ah_[2][4], Al_[2][4];
#pragma unroll
        for (int mi = 0; mi < 2; mi++) {
            u32 aad = aA + (u32)(m0base + mi * 16 + arow) * 272u + (u32)(kt * 32) + acol;
            ldsm4(Ah_[mi], aad);
            ldsm4(Al_[mi], aad + PT_AOFF);
        }
#pragma unroll
        for (int jp = 0; jp < 4; jp++) {
            u32 bad = bB + (u32)(browq + jp * 16) * 272u + (u32)(kt * 32) + bcol;
            u32 Bh_[4], Bl_[4];
            ldsm4(Bh_, bad);
            ldsm4(Bl_, bad + PT_AOFF);
#pragma unroll
            for (int mi = 0; mi < 2; mi++) {
                mma_bf16(acc[mi][2 * jp],     Ah_[mi], Bh_[0], Bh_[1]);
                mma_bf16(acc[mi][2 * jp],     Ah_[mi], Bl_[0], Bl_[1]);
                mma_bf16(acc[mi][2 * jp],     Al_[mi], Bh_[0], Bh_[1]);
                mma_bf16(acc[mi][2 * jp + 1], Ah_[mi], Bh_[2], Bh_[3]);
                mma_bf16(acc[mi][2 * jp + 1], Ah_[mi], Bl_[2], Bl_[3]);
                mma_bf16(acc[mi][2 * jp + 1], Al_[mi], Bh_[2], Bh_[3]);
            }
        }
    }

    const int g2 = lane >> 2, tc = lane & 3;
#pragma unroll
    for (int mi = 0; mi < 2; mi++) {
#pragma unroll
        for (int rh = 0; rh < 2; rh++) {
            const int i = ib + m0base + mi * 16 + g2 + rh * 8;
            const float sqi = g_sq[i];
            const int wti = info[2 * i], gi = info[2 * i + 1];
#pragma unroll
            for (int jl = 0; jl < 8; jl++) {
                const int j0 = jbb + nh * 64 + 8 * jl + 2 * tc;
                float c0 = acc[mi][jl][2 * rh], c1 = acc[mi][jl][2 * rh + 1];
                float2 res;
                {
                    float d2 = sqi + g_sq[j0] - 2.f * c0;
                    float d = sqrtf(fmaxf(d2, 0.f));
                    bool y = (wti == info[2 * j0]) && (gi == 1) && (info[2 * j0 + 1] == 1);
                    float cl = y ? d : fmaxf(1.f - d, 0.f);
                    res.x = (i == j0) ? 0.f : cl;
                }
                {
                    int j1 = j0 + 1;
                    float d2 = sqi + g_sq[j1] - 2.f * c1;
                    float d = sqrtf(fmaxf(d2, 0.f));
                    bool y = (wti == info[2 * j1]) && (gi == 1) && (info[2 * j1 + 1] == 1);
                    float cl = y ? d : fmaxf(1.f - d, 0.f);
                    res.y = (i == j1) ? 0.f : cl;
                }
                *reinterpret_cast<float2*>(out + (size_t)i * 4096 + j0) = res;
            }
        }
    }
}

// ---------------- launch ----------------
extern "C" void kernel_launch(void* const* d_in, const int* in_sizes, int n_in,
                              void* d_out, int out_size) {
    const float* samples = (const float*)d_in[0];
    const int*   info    = (const int*)d_in[1];
    const float* w1  = (const float*)d_in[2];
    const float* b1  = (const float*)d_in[3];
    const float* w2  = (const float*)d_in[4];
    const float* b2  = (const float*)d_in[5];
    const float* w3  = (const float*)d_in[6];
    const float* b3  = (const float*)d_in[7];
    const float* fcw = (const float*)d_in[8];
    const float* fcb = (const float*)d_in[9];
    const float* gam = (const float*)d_in[10];
    const float* bet = (const float*)d_in[11];
    const float* bmu = (const float*)d_in[12];
    const float* bva = (const float*)d_in[13];
    float* out = (float*)d_out;

    cudaFuncSetAttribute(k_conv1, cudaFuncAttributeMaxDynamicSharedMemorySize, C1T_SMEM);
    cudaFuncSetAttribute(k_conv2, cudaFuncAttributeMaxDynamicSharedMemorySize, C2_SMEM);
    cudaFuncSetAttribute(k_conv3, cudaFuncAttributeMaxDynamicSharedMemorySize, C3_SMEM);
    cudaFuncSetAttribute(k_pair,  cudaFuncAttributeMaxDynamicSharedMemorySize, PT_SMEM);

    k_prep_w1<<<4, 256>>>(w1);
    k_prep_w2<<<20, 256>>>(w2);
    k_prep_w3<<<48, 256>>>(w3);
    k_fcT<<<64, 512>>>(fcw);
    k_conv1<<<dim3(NSAMP, 2), 512, C1T_SMEM>>>(samples, b1);
    k_conv2<<<NSAMP, 512, C2_SMEM>>>(b2);
    k_conv3<<<NSAMP, 512, C3_SMEM>>>(b3);
    k_fc<<<NSAMP, 128>>>(fcb, gam, bet, bmu, bva);
    k_pair<<<dim3(32, 32), 256, PT_SMEM>>>(info, out);
}